// round 10
// baseline (speedup 1.0000x reference)
#include <cuda_runtime.h>
#include <cuda_bf16.h>
#include <mma.h>
#include <stdint.h>
#include <math.h>

using namespace nvcuda;

#define MAXN 50000
#define MAXE 800000
#define MAXR 2000
#define FF   128
#define FD   384
#define PP   64
#define EPSV 1e-12f

// ------------------------ scratch (device globals, no allocs) ------------------
__device__ int   g_deg[MAXN];
__device__ int   g_rowptr[MAXN + 1];
__device__ int   g_cursor[MAXN];
__device__ int2  g_edge[MAXE];                  // (src, rel) in CSR-by-dst order
__device__ float g_relnorm[MAXR * FF];
__device__ float g_ttab[4 * MAXR];
__device__ float g_smax[4 * MAXN];
__device__ float g_ssum[4 * MAXN];
__device__ float g_out[2][(size_t)MAXN * FD];   // fp32 concat features
__device__ float g_ssq[2][MAXN];                // exact row sum-of-squares of O
__device__ __nv_bfloat16 g_oh[2][(size_t)MAXN * FD];   // O hi
__device__ __nv_bfloat16 g_ol[2][(size_t)MAXN * FD];   // O lo
__device__ __nv_bfloat16 g_pnh[2][PP * FD];            // l2norm proxy hi
__device__ __nv_bfloat16 g_pnl[2][PP * FD];            // l2norm proxy lo
__device__ __nv_bfloat16 g_ph[2][PP * FD];             // raw proxy hi
__device__ __nv_bfloat16 g_pl[2][PP * FD];             // raw proxy lo
__device__ __nv_bfloat16 g_atth[2][(size_t)MAXN * PP]; // attention hi
__device__ __nv_bfloat16 g_attl[2][(size_t)MAXN * PP]; // attention lo
__device__ __nv_bfloat16 g_pfh[2][(size_t)MAXN * FD];  // proxy_feature hi
__device__ __nv_bfloat16 g_pfl[2][(size_t)MAXN * FD];  // proxy_feature lo
__device__ __nv_bfloat16 g_wh[2][FD * FD];             // gate kernel hi
__device__ __nv_bfloat16 g_wl[2][FD * FD];             // gate kernel lo

__device__ __forceinline__ float wsum(float v) {
#pragma unroll
    for (int o = 16; o; o >>= 1) v += __shfl_xor_sync(0xffffffffu, v, o);
    return v;
}
__device__ __forceinline__ float wmax(float v) {
#pragma unroll
    for (int o = 16; o; o >>= 1) v = fmaxf(v, __shfl_xor_sync(0xffffffffu, v, o));
    return v;
}
__device__ __forceinline__ void split_bf16(float v, __nv_bfloat16& h, __nv_bfloat16& l) {
    h = __float2bfloat16(v);
    l = __float2bfloat16(v - __bfloat162float(h));
}

// ------------------------ CSR build ------------------------
__global__ void zero_deg_kernel(int N_) {
    int i = blockIdx.x * blockDim.x + threadIdx.x;
    if (i < N_) g_deg[i] = 0;
}

__global__ void count_kernel(const int* __restrict__ edst, int E_) {
    int e = blockIdx.x * blockDim.x + threadIdx.x;
    if (e < E_) atomicAdd(&g_deg[edst[e]], 1);
}

__global__ void scan_kernel(int N_) {
    __shared__ int sh[1024];
    __shared__ int carry;
    if (threadIdx.x == 0) carry = 0;
    __syncthreads();
    for (int base = 0; base < N_; base += 1024) {
        int i = base + threadIdx.x;
        int v = (i < N_) ? g_deg[i] : 0;
        sh[threadIdx.x] = v;
        __syncthreads();
#pragma unroll
        for (int off = 1; off < 1024; off <<= 1) {
            int t = (threadIdx.x >= off) ? sh[threadIdx.x - off] : 0;
            __syncthreads();
            sh[threadIdx.x] += t;
            __syncthreads();
        }
        int inc = sh[threadIdx.x];
        int exc = inc - v + carry;
        if (i < N_) { g_rowptr[i] = exc; g_cursor[i] = exc; }
        __syncthreads();
        if (threadIdx.x == 1023) carry += sh[1023];
        __syncthreads();
    }
    if (threadIdx.x == 0) g_rowptr[N_] = carry;
}

__global__ void scatter_kernel(const int* __restrict__ edst,
                               const int* __restrict__ esrc,
                               const int* __restrict__ erel, int E_) {
    int e = blockIdx.x * blockDim.x + threadIdx.x;
    if (e < E_) {
        int p = atomicAdd(&g_cursor[edst[e]], 1);
        g_edge[p] = make_int2(esrc[e], erel[e]);
    }
}

// ------------------------ relation normalization + attn tables ------------------
__global__ void relnorm_kernel(const float* __restrict__ rel,
                               const float* __restrict__ attn_e,
                               const float* __restrict__ attn_r, int R_) {
    int w = (blockIdx.x * blockDim.x + threadIdx.x) >> 5;
    int lane = threadIdx.x & 31;
    if (w >= R_) return;
    float4 v = *(const float4*)(rel + (size_t)w * FF + lane * 4);
    float ss = v.x * v.x + v.y * v.y + v.z * v.z + v.w * v.w;
    ss = wsum(ss);
    float inv = 1.f / fmaxf(sqrtf(ss), EPSV);
    float4 rn = make_float4(v.x * inv, v.y * inv, v.z * inv, v.w * inv);
    *(float4*)(g_relnorm + (size_t)w * FF + lane * 4) = rn;

    float4 a0 = *(const float4*)(attn_e + lane * 4);
    float4 a1 = *(const float4*)(attn_e + FF + lane * 4);
    float4 a2 = *(const float4*)(attn_r + lane * 4);
    float4 a3 = *(const float4*)(attn_r + FF + lane * 4);
    float d0 = wsum(rn.x * a0.x + rn.y * a0.y + rn.z * a0.z + rn.w * a0.w);
    float d1 = wsum(rn.x * a1.x + rn.y * a1.y + rn.z * a1.z + rn.w * a1.w);
    float d2 = wsum(rn.x * a2.x + rn.y * a2.y + rn.z * a2.z + rn.w * a2.w);
    float d3 = wsum(rn.x * a3.x + rn.y * a3.y + rn.z * a3.z + rn.w * a3.w);
    if (lane == 0) {
        g_ttab[0 * R_ + w] = d0;
        g_ttab[1 * R_ + w] = d1;
        g_ttab[2 * R_ + w] = d2;
        g_ttab[3 * R_ + w] = d3;
    }
}

// ------------------------ edge-softmax stats (all 4 tables at once) -------------
__global__ void __launch_bounds__(256) stats_kernel(int N_, int R_) {
    __shared__ float tab[4 * MAXR];
    int tid = threadIdx.x;
    for (int i = tid; i < 4 * R_; i += blockDim.x) tab[i] = g_ttab[i];
    __syncthreads();
    int warp = tid >> 5, lane = tid & 31;
    for (int n = blockIdx.x * 8 + warp; n < N_; n += gridDim.x * 8) {
        int s = g_rowptr[n], e = g_rowptr[n + 1];
        float m0 = -1e30f, m1 = -1e30f, m2 = -1e30f, m3 = -1e30f;
        for (int i = s + lane; i < e; i += 32) {
            int r = g_edge[i].y;
            m0 = fmaxf(m0, tab[r]);
            m1 = fmaxf(m1, tab[R_ + r]);
            m2 = fmaxf(m2, tab[2 * R_ + r]);
            m3 = fmaxf(m3, tab[3 * R_ + r]);
        }
        m0 = wmax(m0); m1 = wmax(m1); m2 = wmax(m2); m3 = wmax(m3);
        float s0 = 0, s1 = 0, s2 = 0, s3 = 0;
        for (int i = s + lane; i < e; i += 32) {
            int r = g_edge[i].y;
            s0 += __expf(tab[r] - m0);
            s1 += __expf(tab[R_ + r] - m1);
            s2 += __expf(tab[2 * R_ + r] - m2);
            s3 += __expf(tab[3 * R_ + r] - m3);
        }
        s0 = wsum(s0); s1 = wsum(s1); s2 = wsum(s2); s3 = wsum(s3);
        if (lane == 0) {
            g_smax[0 * N_ + n] = m0; g_ssum[0 * N_ + n] = s0;
            g_smax[1 * N_ + n] = m1; g_ssum[1 * N_ + n] = s1;
            g_smax[2 * N_ + n] = m2; g_ssum[2 * N_ + n] = s2;
            g_smax[3 * N_ + n] = m3; g_ssum[3 * N_ + n] = s3;
        }
    }
}

// ---------- write O slice helper: fp32 + bf16 hi/lo + return sumsq part ---------
__device__ __forceinline__ float store_slice(int dual, int n, int off,
                                             float t0, float t1, float t2, float t3) {
    float* o = &g_out[dual][(size_t)n * FD + off];
    o[0] = t0; o[1] = t1; o[2] = t2; o[3] = t3;
    __nv_bfloat16 h0, l0, h1, l1, h2, l2, h3, l3;
    split_bf16(t0, h0, l0); split_bf16(t1, h1, l1);
    split_bf16(t2, h2, l2); split_bf16(t3, h3, l3);
    size_t bi = ((size_t)n * FD + off) >> 1;
    __nv_bfloat162* OH = (__nv_bfloat162*)g_oh[dual];
    __nv_bfloat162* OL = (__nv_bfloat162*)g_ol[dual];
    OH[bi] = __nv_bfloat162(h0, h1); OH[bi + 1] = __nv_bfloat162(h2, h3);
    OL[bi] = __nv_bfloat162(l0, l1); OL[bi + 1] = __nv_bfloat162(l2, l3);
    return t0 * t0 + t1 * t1 + t2 * t2 + t3 * t3;
}

// ---------- initial mean features: 1 warp/node, lane=float4, 2-edge ILP ---------
__global__ void __launch_bounds__(256) init_kernel(const float* __restrict__ ent,
                                                   const float* __restrict__ rel, int N_) {
    int w = (blockIdx.x * blockDim.x + threadIdx.x) >> 5;
    if (w >= N_) return;
    int lane = threadIdx.x & 31;
    int s = g_rowptr[w], e = g_rowptr[w + 1];
    float4 ae = make_float4(0, 0, 0, 0), ar = make_float4(0, 0, 0, 0);
    int i = s;
    for (; i + 1 < e; i += 2) {
        int2 e0 = g_edge[i], e1 = g_edge[i + 1];
        float4 a = *(const float4*)(ent + (size_t)e0.x * FF + lane * 4);
        float4 b = *(const float4*)(rel + (size_t)e0.y * FF + lane * 4);
        float4 c = *(const float4*)(ent + (size_t)e1.x * FF + lane * 4);
        float4 d = *(const float4*)(rel + (size_t)e1.y * FF + lane * 4);
        ae.x += a.x + c.x; ae.y += a.y + c.y; ae.z += a.z + c.z; ae.w += a.w + c.w;
        ar.x += b.x + d.x; ar.y += b.y + d.y; ar.z += b.z + d.z; ar.w += b.w + d.w;
    }
    if (i < e) {
        int2 e0 = g_edge[i];
        float4 a = *(const float4*)(ent + (size_t)e0.x * FF + lane * 4);
        float4 b = *(const float4*)(rel + (size_t)e0.y * FF + lane * 4);
        ae.x += a.x; ae.y += a.y; ae.z += a.z; ae.w += a.w;
        ar.x += b.x; ar.y += b.y; ar.z += b.z; ar.w += b.w;
    }
    float inv = 1.f / fmaxf((float)(e - s), 1.f);
    float se = store_slice(0, w, lane * 4, tanhf(ae.x * inv), tanhf(ae.y * inv),
                           tanhf(ae.z * inv), tanhf(ae.w * inv));
    float sr = store_slice(1, w, lane * 4, tanhf(ar.x * inv), tanhf(ar.y * inv),
                           tanhf(ar.z * inv), tanhf(ar.w * inv));
    se = wsum(se);
    sr = wsum(sr);
    if (lane == 0) { g_ssq[0][w] = se; g_ssq[1][w] = sr; }
}

// ---------- GNN layer: 1 warp/node, lane=float4 (coalesced), 4-edge ILP ---------
__global__ void __launch_bounds__(256) layer_kernel(int layer, int N_, int R_) {
    int gw = (blockIdx.x * blockDim.x + threadIdx.x) >> 5;
    if (gw >= 2 * N_) return;
    int dual = gw >= N_;
    int w = gw - dual * N_;
    int lane = threadIdx.x & 31;
    int s = g_rowptr[w], e = g_rowptr[w + 1];
    int t = dual * 2 + layer;
    const float* feats = g_out[dual];
    const float* tt = g_ttab + (size_t)t * R_;
    float smax = g_smax[(size_t)t * N_ + w];
    float invs = (e > s) ? 1.f / g_ssum[(size_t)t * N_ + w] : 0.f;
    int coff = layer * FF + lane * 4;
    float4 acc = make_float4(0, 0, 0, 0);

    for (int i = s; i < e; i += 4) {
        int i1 = min(i + 1, e - 1), i2 = min(i + 2, e - 1), i3 = min(i + 3, e - 1);
        float a1 = (i + 1 < e) ? 1.f : 0.f;
        float a2 = (i + 2 < e) ? 1.f : 0.f;
        float a3 = (i + 3 < e) ? 1.f : 0.f;
        int2 e0 = g_edge[i], e1 = g_edge[i1], e2 = g_edge[i2], e3 = g_edge[i3];
        float4 f0 = *(const float4*)(feats + (size_t)e0.x * FD + coff);
        float4 f1 = *(const float4*)(feats + (size_t)e1.x * FD + coff);
        float4 f2 = *(const float4*)(feats + (size_t)e2.x * FD + coff);
        float4 f3 = *(const float4*)(feats + (size_t)e3.x * FD + coff);
        float4 r0 = *(const float4*)(g_relnorm + (size_t)e0.y * FF + lane * 4);
        float4 r1 = *(const float4*)(g_relnorm + (size_t)e1.y * FF + lane * 4);
        float4 r2 = *(const float4*)(g_relnorm + (size_t)e2.y * FF + lane * 4);
        float4 r3 = *(const float4*)(g_relnorm + (size_t)e3.y * FF + lane * 4);
        float p0 = f0.x * r0.x + f0.y * r0.y + f0.z * r0.z + f0.w * r0.w;
        float p1 = f1.x * r1.x + f1.y * r1.y + f1.z * r1.z + f1.w * r1.w;
        float p2 = f2.x * r2.x + f2.y * r2.y + f2.z * r2.z + f2.w * r2.w;
        float p3 = f3.x * r3.x + f3.y * r3.y + f3.z * r3.z + f3.w * r3.w;
#pragma unroll
        for (int o = 16; o; o >>= 1) {
            p0 += __shfl_xor_sync(0xffffffffu, p0, o);
            p1 += __shfl_xor_sync(0xffffffffu, p1, o);
            p2 += __shfl_xor_sync(0xffffffffu, p2, o);
            p3 += __shfl_xor_sync(0xffffffffu, p3, o);
        }
        float w0 = __expf(tt[e0.y] - smax) * invs;
        float w1 = __expf(tt[e1.y] - smax) * invs * a1;
        float w2 = __expf(tt[e2.y] - smax) * invs * a2;
        float w3 = __expf(tt[e3.y] - smax) * invs * a3;
        float c0 = 2.f * p0 * w0, c1 = 2.f * p1 * w1;
        float c2 = 2.f * p2 * w2, c3 = 2.f * p3 * w3;
        acc.x += w0 * f0.x - c0 * r0.x + w1 * f1.x - c1 * r1.x
               + w2 * f2.x - c2 * r2.x + w3 * f3.x - c3 * r3.x;
        acc.y += w0 * f0.y - c0 * r0.y + w1 * f1.y - c1 * r1.y
               + w2 * f2.y - c2 * r2.y + w3 * f3.y - c3 * r3.y;
        acc.z += w0 * f0.z - c0 * r0.z + w1 * f1.z - c1 * r1.z
               + w2 * f2.z - c2 * r2.z + w3 * f3.z - c3 * r3.z;
        acc.w += w0 * f0.w - c0 * r0.w + w1 * f1.w - c1 * r1.w
               + w2 * f2.w - c2 * r2.w + w3 * f3.w - c3 * r3.w;
    }
    float sq = store_slice(dual, w, (layer + 1) * FF + lane * 4,
                           tanhf(acc.x), tanhf(acc.y), tanhf(acc.z), tanhf(acc.w));
    sq = wsum(sq);
    if (lane == 0) g_ssq[dual][w] += sq;
}

// --------- proxy normalization: write normalized + raw bf16 hi/lo ---------------
__global__ void pnorm_kernel(const float* __restrict__ pe, const float* __restrict__ pr) {
    int w = (blockIdx.x * blockDim.x + threadIdx.x) >> 5;
    if (w >= 2 * PP) return;
    int lane = threadIdx.x & 31;
    int dual = (w >= PP) ? 1 : 0;
    int row = w & (PP - 1);
    const float* p = dual ? pr : pe;
    float v[12];
    float ss = 0;
#pragma unroll
    for (int j = 0; j < 12; j++) {
        v[j] = p[(size_t)row * FD + lane + 32 * j];
        ss += v[j] * v[j];
    }
    ss = wsum(ss);
    float inv = 1.f / fmaxf(sqrtf(ss), EPSV);
#pragma unroll
    for (int j = 0; j < 12; j++) {
        int idx = row * FD + lane + 32 * j;
        __nv_bfloat16 h, l;
        split_bf16(v[j] * inv, h, l);
        g_pnh[dual][idx] = h; g_pnl[dual][idx] = l;
        split_bf16(v[j], h, l);
        g_ph[dual][idx] = h; g_pl[dual][idx] = l;
    }
}

// ------------------------ W -> bf16 hi/lo split ---------------------------------
__global__ void wconv_kernel(const float* __restrict__ We, const float* __restrict__ Wr) {
    int i = blockIdx.x * blockDim.x + threadIdx.x;
    if (i >= 2 * FD * FD) return;
    int dual = i >= FD * FD;
    int j = i - dual * FD * FD;
    float v = (dual ? Wr : We)[j];
    __nv_bfloat16 h, l;
    split_bf16(v, h, l);
    g_wh[dual][j] = h;
    g_wl[dual][j] = l;
}

#define ALD 40
#define SLD 68
#define BLD 72

// ------- S = l2norm(O) @ Pn^T (WMMA 3-term) + fused softmax -> att hi/lo --------
__global__ void __launch_bounds__(256) s_wmma_kernel(int N_) {
    __shared__ __align__(16) char smraw[34816];
    __nv_bfloat16* Ah = (__nv_bfloat16*)smraw;           // [128][ALD]
    __nv_bfloat16* Al = Ah + 128 * ALD;
    __nv_bfloat16* Bh = Al + 128 * ALD;                  // [64][ALD]
    __nv_bfloat16* Bl = Bh + 64 * ALD;
    float* stage = (float*)smraw;                        // [128][SLD]

    int tid = threadIdx.x, wid = tid >> 5, lane = tid & 31;
    int warpM = wid & 3, warpN = wid >> 2;
    int rowBase = blockIdx.x * 128;
    int dual = blockIdx.z;
    const unsigned* OH = (const unsigned*)g_oh[dual];
    const unsigned* OL = (const unsigned*)g_ol[dual];
    const unsigned* PNH = (const unsigned*)g_pnh[dual];
    const unsigned* PNL = (const unsigned*)g_pnl[dual];

    wmma::fragment<wmma::accumulator, 16, 16, 16, float> c[2][2];
#pragma unroll
    for (int i = 0; i < 2; i++)
#pragma unroll
        for (int j = 0; j < 2; j++) wmma::fill_fragment(c[i][j], 0.f);

    for (int k0 = 0; k0 < FD; k0 += 32) {
        for (int s = tid; s < 2048; s += 256) {
            int r = s >> 4, cu = s & 15;
            int gr = rowBase + r;
            unsigned vh = 0, vl = 0;
            if (gr < N_) {
                size_t gi = ((size_t)gr * FD + k0) / 2 + cu;
                vh = OH[gi]; vl = OL[gi];
            }
            ((unsigned*)(Ah + r * ALD))[cu] = vh;
            ((unsigned*)(Al + r * ALD))[cu] = vl;
        }
        for (int s = tid; s < 1024; s += 256) {
            int r = s >> 4, cu = s & 15;
            size_t gi = ((size_t)r * FD + k0) / 2 + cu;
            ((unsigned*)(Bh + r * ALD))[cu] = PNH[gi];
            ((unsigned*)(Bl + r * ALD))[cu] = PNL[gi];
        }
        __syncthreads();
#pragma unroll
        for (int ks = 0; ks < 32; ks += 16) {
            wmma::fragment<wmma::matrix_a, 16, 16, 16, __nv_bfloat16, wmma::row_major> a[2];
            wmma::fragment<wmma::matrix_b, 16, 16, 16, __nv_bfloat16, wmma::col_major> b[2];
#pragma unroll
            for (int i = 0; i < 2; i++)
                wmma::load_matrix_sync(a[i], Ah + (warpM * 32 + i * 16) * ALD + ks, ALD);
#pragma unroll
            for (int j = 0; j < 2; j++)
                wmma::load_matrix_sync(b[j], Bh + (warpN * 32 + j * 16) * ALD + ks, ALD);
#pragma unroll
            for (int i = 0; i < 2; i++)
#pragma unroll
                for (int j = 0; j < 2; j++) wmma::mma_sync(c[i][j], a[i], b[j], c[i][j]);
#pragma unroll
            for (int i = 0; i < 2; i++)
                wmma::load_matrix_sync(a[i], Al + (warpM * 32 + i * 16) * ALD + ks, ALD);
#pragma unroll
            for (int i = 0; i < 2; i++)
#pragma unroll
                for (int j = 0; j < 2; j++) wmma::mma_sync(c[i][j], a[i], b[j], c[i][j]);
#pragma unroll
            for (int i = 0; i < 2; i++)
                wmma::load_matrix_sync(a[i], Ah + (warpM * 32 + i * 16) * ALD + ks, ALD);
#pragma unroll
            for (int j = 0; j < 2; j++)
                wmma::load_matrix_sync(b[j], Bl + (warpN * 32 + j * 16) * ALD + ks, ALD);
#pragma unroll
            for (int i = 0; i < 2; i++)
#pragma unroll
                for (int j = 0; j < 2; j++) wmma::mma_sync(c[i][j], a[i], b[j], c[i][j]);
        }
        __syncthreads();
    }

#pragma unroll
    for (int i = 0; i < 2; i++)
#pragma unroll
        for (int j = 0; j < 2; j++)
            wmma::store_matrix_sync(stage + (warpM * 32 + i * 16) * SLD + warpN * 32 + j * 16,
                                    c[i][j], SLD, wmma::mem_row_major);
    __syncthreads();

    // fused: scale by 1/||O||, softmax over 64 proxies, write att bf16 hi/lo
    __nv_bfloat162* ATTH = (__nv_bfloat162*)g_atth[dual];
    __nv_bfloat162* ATTL = (__nv_bfloat162*)g_attl[dual];
#pragma unroll
    for (int i = 0; i < 16; i++) {
        int r = wid * 16 + i;
        int n = rowBase + r;
        float inv = 0.f;
        if (n < N_) inv = 1.f / fmaxf(sqrtf(g_ssq[dual][n]), EPSV);
        float v0 = stage[r * SLD + lane * 2] * inv;
        float v1 = stage[r * SLD + lane * 2 + 1] * inv;
        float m = fmaxf(v0, v1);
#pragma unroll
        for (int o = 16; o; o >>= 1) m = fmaxf(m, __shfl_xor_sync(0xffffffffu, m, o));
        float e0 = __expf(v0 - m), e1 = __expf(v1 - m);
        float sm = e0 + e1;
#pragma unroll
        for (int o = 16; o; o >>= 1) sm += __shfl_xor_sync(0xffffffffu, sm, o);
        float rc = 1.f / sm;
        if (n < N_) {
            float a0 = e0 * rc, a1 = e1 * rc;
            __nv_bfloat16 h0, l0, h1, l1;
            split_bf16(a0, h0, l0);
            split_bf16(a1, h1, l1);
            size_t bi = ((size_t)n * PP + lane * 2) >> 1;
            ATTH[bi] = __nv_bfloat162(h0, h1);
            ATTL[bi] = __nv_bfloat162(l0, l1);
        }
    }
}

// ------- PF = O - Att @ P (WMMA 3-term, K=64) -> bf16 hi/lo ---------------------
__global__ void __launch_bounds__(256) pf_wmma_kernel(int N_) {
    __shared__ __align__(16) char smraw[34816];
    __nv_bfloat16* Ah = (__nv_bfloat16*)smraw;           // [128][ALD]
    __nv_bfloat16* Al = Ah + 128 * ALD;
    __nv_bfloat16* Bh = Al + 128 * ALD;                  // [32 k][BLD cols]
    __nv_bfloat16* Bl = Bh + 32 * BLD;
    float* stage = (float*)smraw;                        // [128][SLD]

    int tid = threadIdx.x, wid = tid >> 5, lane = tid & 31;
    int warpM = wid & 3, warpN = wid >> 2;
    int colBase = blockIdx.x * 64;
    int rowBase = blockIdx.y * 128;
    int dual = blockIdx.z;
    const unsigned* ATH = (const unsigned*)g_atth[dual];
    const unsigned* ATL = (const unsigned*)g_attl[dual];
    const unsigned* PH = (const unsigned*)g_ph[dual];
    const unsigned* PL = (const unsigned*)g_pl[dual];

    wmma::fragment<wmma::accumulator, 16, 16, 16, float> c[2][2];
#pragma unroll
    for (int i = 0; i < 2; i++)
#pragma unroll
        for (int j = 0; j < 2; j++) wmma::fill_fragment(c[i][j], 0.f);

    for (int k0 = 0; k0 < PP; k0 += 32) {
        for (int s = tid; s < 2048; s += 256) {
            int r = s >> 4, cu = s & 15;
            int gr = rowBase + r;
            unsigned vh = 0, vl = 0;
            if (gr < N_) {
                size_t gi = ((size_t)gr * PP + k0) / 2 + cu;
                vh = ATH[gi]; vl = ATL[gi];
            }
            ((unsigned*)(Ah + r * ALD))[cu] = vh;
            ((unsigned*)(Al + r * ALD))[cu] = vl;
        }
        for (int s = tid; s < 1024; s += 256) {
            int k = s >> 5, cp = s & 31;
            size_t gi = ((size_t)(k0 + k) * FD + colBase) / 2 + cp;
            ((unsigned*)(Bh + k * BLD))[cp] = PH[gi];
            ((unsigned*)(Bl + k * BLD))[cp] = PL[gi];
        }
        __syncthreads();
#pragma unroll
        for (int ks = 0; ks < 32; ks += 16) {
            wmma::fragment<wmma::matrix_a, 16, 16, 16, __nv_bfloat16, wmma::row_major> a[2];
            wmma::fragment<wmma::matrix_b, 16, 16, 16, __nv_bfloat16, wmma::row_major> b[2];
#pragma unroll
            for (int i = 0; i < 2; i++)
                wmma::load_matrix_sync(a[i], Ah + (warpM * 32 + i * 16) * ALD + ks, ALD);
#pragma unroll
            for (int j = 0; j < 2; j++)
                wmma::load_matrix_sync(b[j], Bh + ks * BLD + warpN * 32 + j * 16, BLD);
#pragma unroll
            for (int i = 0; i < 2; i++)
#pragma unroll
                for (int j = 0; j < 2; j++) wmma::mma_sync(c[i][j], a[i], b[j], c[i][j]);
#pragma unroll
            for (int i = 0; i < 2; i++)
                wmma::load_matrix_sync(a[i], Al + (warpM * 32 + i * 16) * ALD + ks, ALD);
#pragma unroll
            for (int i = 0; i < 2; i++)
#pragma unroll
                for (int j = 0; j < 2; j++) wmma::mma_sync(c[i][j], a[i], b[j], c[i][j]);
#pragma unroll
            for (int i = 0; i < 2; i++)
                wmma::load_matrix_sync(a[i], Ah + (warpM * 32 + i * 16) * ALD + ks, ALD);
#pragma unroll
            for (int j = 0; j < 2; j++)
                wmma::load_matrix_sync(b[j], Bl + ks * BLD + warpN * 32 + j * 16, BLD);
#pragma unroll
            for (int i = 0; i < 2; i++)
#pragma unroll
                for (int j = 0; j < 2; j++) wmma::mma_sync(c[i][j], a[i], b[j], c[i][j]);
        }
        __syncthreads();
    }

#pragma unroll
    for (int i = 0; i < 2; i++)
#pragma unroll
        for (int j = 0; j < 2; j++)
            wmma::store_matrix_sync(stage + (warpM * 32 + i * 16) * SLD + warpN * 32 + j * 16,
                                    c[i][j], SLD, wmma::mem_row_major);
    __syncthreads();

    const float* O = g_out[dual];
    __nv_bfloat162* DH = (__nv_bfloat162*)g_pfh[dual];
    __nv_bfloat162* DL = (__nv_bfloat162*)g_pfl[dual];
#pragma unroll
    for (int i = 0; i < 16; i++) {
        int r = wid * 16 + i;
        int n = rowBase + r;
        if (n >= N_) continue;
        int c0 = colBase + lane * 2;
        float2 acc = *(float2*)(stage + r * SLD + lane * 2);
        float2 ov = *(const float2*)(O + (size_t)n * FD + c0);
        float va = ov.x - acc.x;
        float vb = ov.y - acc.y;
        __nv_bfloat16 ha, la, hb, lb;
        split_bf16(va, ha, la);
        split_bf16(vb, hb, lb);
        size_t bi = ((size_t)n * FD + c0) >> 1;
        DH[bi] = __nv_bfloat162(ha, hb);
        DL[bi] = __nv_bfloat162(la, lb);
    }
}

// ------- F2: WMMA bf16 3-term split GEMM + sigmoid blend ------------------------
__global__ void __launch_bounds__(256) f2_wmma_kernel(const float* __restrict__ be,
                                                      const float* __restrict__ br,
                                                      float* __restrict__ out, int N_) {
    __shared__ __align__(16) char smraw[34816];
    __nv_bfloat16* Ah = (__nv_bfloat16*)smraw;           // [128][ALD]
    __nv_bfloat16* Al = Ah + 128 * ALD;
    __nv_bfloat16* Bh = Al + 128 * ALD;                  // [64][ALD] (n-major, k inner)
    __nv_bfloat16* Bl = Bh + 64 * ALD;
    float* stage = (float*)smraw;                        // [128][SLD]

    int tid = threadIdx.x, wid = tid >> 5, lane = tid & 31;
    int warpM = wid & 3, warpN = wid >> 2;
    int colBase = blockIdx.x * 64;
    int rowBase = blockIdx.y * 128;
    int dual = blockIdx.z;
    const float* bias = dual ? br : be;
    const __nv_bfloat16* PH = g_pfh[dual];
    const __nv_bfloat16* PL = g_pfl[dual];
    const __nv_bfloat16* WH = g_wh[dual];
    const __nv_bfloat16* WL = g_wl[dual];

    wmma::fragment<wmma::accumulator, 16, 16, 16, float> c[2][2];
#pragma unroll
    for (int i = 0; i < 2; i++)
#pragma unroll
        for (int j = 0; j < 2; j++) wmma::fill_fragment(c[i][j], 0.f);

    for (int k0 = 0; k0 < FD; k0 += 32) {
        for (int s = tid; s < 2048; s += 256) {
            int r = s >> 4, cu = s & 15;
            int gr = rowBase + r;
            unsigned vh = 0, vl = 0;
            if (gr < N_) {
                size_t gi = ((size_t)gr * FD + k0) / 2 + cu;
                vh = ((const unsigned*)PH)[gi];
                vl = ((const unsigned*)PL)[gi];
            }
            ((unsigned*)(Ah + r * ALD))[cu] = vh;
            ((unsigned*)(Al + r * ALD))[cu] = vl;
        }
        for (int s = tid; s < 64 * 32; s += 256) {
            int n = s & 63, k = s >> 6;
            size_t gi = (size_t)(k0 + k) * FD + colBase + n;
            Bh[n * ALD + k] = WH[gi];
            Bl[n * ALD + k] = WL[gi];
        }
        __syncthreads();
#pragma unroll
        for (int ks = 0; ks < 32; ks += 16) {
            wmma::fragment<wmma::matrix_a, 16, 16, 16, __nv_bfloat16, wmma::row_major> a[2];
            wmma::fragment<wmma::matrix_b, 16, 16, 16, __nv_bfloat16, wmma::col_major> b[2];
#pragma unroll
            for (int i = 0; i < 2; i++)
                wmma::load_matrix_sync(a[i], Ah + (warpM * 32 + i * 16) * ALD + ks, ALD);
#pragma unroll
            for (int j = 0; j < 2; j++)
                wmma::load_matrix_sync(b[j], Bh + (warpN * 32 + j * 16) * ALD + ks, ALD);
#pragma unroll
            for (int i = 0; i < 2; i++)
#pragma unroll
                for (int j = 0; j < 2; j++) wmma::mma_sync(c[i][j], a[i], b[j], c[i][j]);
#pragma unroll
            for (int i = 0; i < 2; i++)
                wmma::load_matrix_sync(a[i], Al + (warpM * 32 + i * 16) * ALD + ks, ALD);
#pragma unroll
            for (int i = 0; i < 2; i++)
#pragma unroll
                for (int j = 0; j < 2; j++) wmma::mma_sync(c[i][j], a[i], b[j], c[i][j]);
#pragma unroll
            for (int i = 0; i < 2; i++)
                wmma::load_matrix_sync(a[i], Ah + (warpM * 32 + i * 16) * ALD + ks, ALD);
#pragma unroll
            for (int j = 0; j < 2; j++)
                wmma::load_matrix_sync(b[j], Bl + (warpN * 32 + j * 16) * ALD + ks, ALD);
#pragma unroll
            for (int i = 0; i < 2; i++)
#pragma unroll
                for (int j = 0; j < 2; j++) wmma::mma_sync(c[i][j], a[i], b[j], c[i][j]);
        }
        __syncthreads();
    }

#pragma unroll
    for (int i = 0; i < 2; i++)
#pragma unroll
        for (int j = 0; j < 2; j++)
            wmma::store_matrix_sync(stage + (warpM * 32 + i * 16) * SLD + warpN * 32 + j * 16,
                                    c[i][j], SLD, wmma::mem_row_major);
    __syncthreads();

    const float* O = g_out[dual];
    const __nv_bfloat162* PH2 = (const __nv_bfloat162*)PH;
    const __nv_bfloat162* PL2 = (const __nv_bfloat162*)PL;
#pragma unroll
    for (int i = 0; i < 16; i++) {
        int r = wid * 16 + i;
        int n = rowBase + r;
        if (n >= N_) continue;
        int c0 = colBase + lane * 2;
        float2 acc = *(float2*)(stage + r * SLD + lane * 2);
        float2 bv = *(const float2*)(bias + c0);
        float2 ov = *(const float2*)(O + (size_t)n * FD + c0);
        size_t pi = ((size_t)n * FD + c0) >> 1;
        __nv_bfloat162 h0 = PH2[pi];
        __nv_bfloat162 l0 = PL2[pi];
        float pf0 = __bfloat162float(h0.x) + __bfloat162float(l0.x);
        float pf1 = __bfloat162float(h0.y) + __bfloat162float(l0.y);
        float g0 = 1.f / (1.f + __expf(-(acc.x + bv.x)));
        float g1 = 1.f / (1.f + __expf(-(acc.y + bv.y)));
        float2 res;
        res.x = g0 * ov.x + (1.f - g0) * pf0;
        res.y = g1 * ov.y + (1.f - g1) * pf1;
        *(float2*)(out + (size_t)n * (2 * FD) + dual * FD + c0) = res;
    }
}

// ------------------------ launch ------------------------------------------------
extern "C" void kernel_launch(void* const* d_in, const int* in_sizes, int n_in,
                              void* d_out, int out_size) {
    const float* ent_emb = (const float*)d_in[0];
    const float* rel_emb = (const float*)d_in[1];
    const int* edge_src  = (const int*)d_in[2];
    const int* edge_dst  = (const int*)d_in[3];
    const int* edge_rel  = (const int*)d_in[4];
    const float* attn_e  = (const float*)d_in[5];
    const float* gate_e  = (const float*)d_in[6];
    const float* proxy_e = (const float*)d_in[7];
    const float* bias_e  = (const float*)d_in[8];
    const float* attn_r  = (const float*)d_in[9];
    const float* gate_r  = (const float*)d_in[10];
    const float* proxy_r = (const float*)d_in[11];
    const float* bias_r  = (const float*)d_in[12];

    int N_ = in_sizes[0] / FF;
    int R_ = in_sizes[1] / FF;
    int E_ = in_sizes[2];
    float* out = (float*)d_out;

    zero_deg_kernel<<<(N_ + 255) / 256, 256>>>(N_);
    count_kernel<<<(E_ + 255) / 256, 256>>>(edge_dst, E_);
    scan_kernel<<<1, 1024>>>(N_);
    scatter_kernel<<<(E_ + 255) / 256, 256>>>(edge_dst, edge_src, edge_rel, E_);
    relnorm_kernel<<<(R_ * 32 + 255) / 256, 256>>>(rel_emb, attn_e, attn_r, R_);
    stats_kernel<<<1184, 256>>>(N_, R_);
    init_kernel<<<(N_ * 32 + 255) / 256, 256>>>(ent_emb, rel_emb, N_);
    wconv_kernel<<<(2 * FD * FD + 255) / 256, 256>>>(gate_e, gate_r);
    pnorm_kernel<<<16, 256>>>(proxy_e, proxy_r);

    int lgrid = (2 * N_ * 32 + 255) / 256;
    layer_kernel<<<lgrid, 256>>>(0, N_, R_);
    layer_kernel<<<lgrid, 256>>>(1, N_, R_);

    int rb = (N_ + 127) / 128;
    dim3 gs(rb, 1, 2);
    s_wmma_kernel<<<gs, 256>>>(N_);

    dim3 gpf(FD / 64, rb, 2);
    pf_wmma_kernel<<<gpf, 256>>>(N_);

    dim3 g2(FD / 64, rb, 2);
    f2_wmma_kernel<<<g2, 256>>>(bias_e, bias_r, out, N_);
}

// round 11
// speedup vs baseline: 1.0930x; 1.0930x over previous
#include <cuda_runtime.h>
#include <cuda_bf16.h>
#include <mma.h>
#include <stdint.h>
#include <math.h>

using namespace nvcuda;

#define MAXN 50000
#define MAXE 800000
#define MAXR 2000
#define FF   128
#define FD   384
#define PP   64
#define EPSV 1e-12f

// ------------------------ scratch (device globals, no allocs) ------------------
__device__ int   g_deg[MAXN];
__device__ int   g_rowptr[MAXN + 1];
__device__ int   g_cursor[MAXN];
__device__ int2  g_edge[MAXE];                  // (src, rel) in CSR-by-dst order
__device__ float g_relnorm[MAXR * FF];
__device__ float g_ttab[4 * MAXR];
__device__ float g_smax[4 * MAXN];
__device__ float g_ssum[4 * MAXN];
__device__ float g_out[2][(size_t)MAXN * FD];   // fp32 concat features
__device__ __nv_bfloat16 g_pnh[2][PP * FD];            // l2norm proxy hi
__device__ __nv_bfloat16 g_pnl[2][PP * FD];            // l2norm proxy lo
__device__ __nv_bfloat16 g_ph[2][PP * FD];             // raw proxy hi
__device__ __nv_bfloat16 g_pl[2][PP * FD];             // raw proxy lo
__device__ __nv_bfloat16 g_atth[2][(size_t)MAXN * PP]; // attention hi
__device__ __nv_bfloat16 g_attl[2][(size_t)MAXN * PP]; // attention lo
__device__ __nv_bfloat16 g_pfh[2][(size_t)MAXN * FD];  // proxy_feature hi
__device__ __nv_bfloat16 g_pfl[2][(size_t)MAXN * FD];  // proxy_feature lo
__device__ __nv_bfloat16 g_wh[2][FD * FD];             // gate kernel hi
__device__ __nv_bfloat16 g_wl[2][FD * FD];             // gate kernel lo

__device__ __forceinline__ float wsum(float v) {
#pragma unroll
    for (int o = 16; o; o >>= 1) v += __shfl_xor_sync(0xffffffffu, v, o);
    return v;
}
__device__ __forceinline__ float wmax(float v) {
#pragma unroll
    for (int o = 16; o; o >>= 1) v = fmaxf(v, __shfl_xor_sync(0xffffffffu, v, o));
    return v;
}
__device__ __forceinline__ void split_bf16(float v, __nv_bfloat16& h, __nv_bfloat16& l) {
    h = __float2bfloat16(v);
    l = __float2bfloat16(v - __bfloat162float(h));
}

// ------------------------ CSR build ------------------------
__global__ void zero_deg_kernel(int N_) {
    int i = blockIdx.x * blockDim.x + threadIdx.x;
    if (i < N_) g_deg[i] = 0;
}

__global__ void count_kernel(const int* __restrict__ edst, int E_) {
    int e = blockIdx.x * blockDim.x + threadIdx.x;
    if (e < E_) atomicAdd(&g_deg[edst[e]], 1);
}

__global__ void scan_kernel(int N_) {
    __shared__ int sh[1024];
    __shared__ int carry;
    if (threadIdx.x == 0) carry = 0;
    __syncthreads();
    for (int base = 0; base < N_; base += 1024) {
        int i = base + threadIdx.x;
        int v = (i < N_) ? g_deg[i] : 0;
        sh[threadIdx.x] = v;
        __syncthreads();
#pragma unroll
        for (int off = 1; off < 1024; off <<= 1) {
            int t = (threadIdx.x >= off) ? sh[threadIdx.x - off] : 0;
            __syncthreads();
            sh[threadIdx.x] += t;
            __syncthreads();
        }
        int inc = sh[threadIdx.x];
        int exc = inc - v + carry;
        if (i < N_) { g_rowptr[i] = exc; g_cursor[i] = exc; }
        __syncthreads();
        if (threadIdx.x == 1023) carry += sh[1023];
        __syncthreads();
    }
    if (threadIdx.x == 0) g_rowptr[N_] = carry;
}

__global__ void scatter_kernel(const int* __restrict__ edst,
                               const int* __restrict__ esrc,
                               const int* __restrict__ erel, int E_) {
    int e = blockIdx.x * blockDim.x + threadIdx.x;
    if (e < E_) {
        int p = atomicAdd(&g_cursor[edst[e]], 1);
        g_edge[p] = make_int2(esrc[e], erel[e]);
    }
}

// ------------------------ relation normalization + attn tables ------------------
__global__ void relnorm_kernel(const float* __restrict__ rel,
                               const float* __restrict__ attn_e,
                               const float* __restrict__ attn_r, int R_) {
    int w = (blockIdx.x * blockDim.x + threadIdx.x) >> 5;
    int lane = threadIdx.x & 31;
    if (w >= R_) return;
    float4 v = *(const float4*)(rel + (size_t)w * FF + lane * 4);
    float ss = v.x * v.x + v.y * v.y + v.z * v.z + v.w * v.w;
    ss = wsum(ss);
    float inv = 1.f / fmaxf(sqrtf(ss), EPSV);
    float4 rn = make_float4(v.x * inv, v.y * inv, v.z * inv, v.w * inv);
    *(float4*)(g_relnorm + (size_t)w * FF + lane * 4) = rn;

    float4 a0 = *(const float4*)(attn_e + lane * 4);
    float4 a1 = *(const float4*)(attn_e + FF + lane * 4);
    float4 a2 = *(const float4*)(attn_r + lane * 4);
    float4 a3 = *(const float4*)(attn_r + FF + lane * 4);
    float d0 = wsum(rn.x * a0.x + rn.y * a0.y + rn.z * a0.z + rn.w * a0.w);
    float d1 = wsum(rn.x * a1.x + rn.y * a1.y + rn.z * a1.z + rn.w * a1.w);
    float d2 = wsum(rn.x * a2.x + rn.y * a2.y + rn.z * a2.z + rn.w * a2.w);
    float d3 = wsum(rn.x * a3.x + rn.y * a3.y + rn.z * a3.z + rn.w * a3.w);
    if (lane == 0) {
        g_ttab[0 * R_ + w] = d0;
        g_ttab[1 * R_ + w] = d1;
        g_ttab[2 * R_ + w] = d2;
        g_ttab[3 * R_ + w] = d3;
    }
}

// ------------------------ edge-softmax stats (all 4 tables at once) -------------
__global__ void __launch_bounds__(256) stats_kernel(int N_, int R_) {
    __shared__ float tab[4 * MAXR];
    int tid = threadIdx.x;
    for (int i = tid; i < 4 * R_; i += blockDim.x) tab[i] = g_ttab[i];
    __syncthreads();
    int warp = tid >> 5, lane = tid & 31;
    for (int n = blockIdx.x * 8 + warp; n < N_; n += gridDim.x * 8) {
        int s = g_rowptr[n], e = g_rowptr[n + 1];
        float m0 = -1e30f, m1 = -1e30f, m2 = -1e30f, m3 = -1e30f;
        for (int i = s + lane; i < e; i += 32) {
            int r = g_edge[i].y;
            m0 = fmaxf(m0, tab[r]);
            m1 = fmaxf(m1, tab[R_ + r]);
            m2 = fmaxf(m2, tab[2 * R_ + r]);
            m3 = fmaxf(m3, tab[3 * R_ + r]);
        }
        m0 = wmax(m0); m1 = wmax(m1); m2 = wmax(m2); m3 = wmax(m3);
        float s0 = 0, s1 = 0, s2 = 0, s3 = 0;
        for (int i = s + lane; i < e; i += 32) {
            int r = g_edge[i].y;
            s0 += __expf(tab[r] - m0);
            s1 += __expf(tab[R_ + r] - m1);
            s2 += __expf(tab[2 * R_ + r] - m2);
            s3 += __expf(tab[3 * R_ + r] - m3);
        }
        s0 = wsum(s0); s1 = wsum(s1); s2 = wsum(s2); s3 = wsum(s3);
        if (lane == 0) {
            g_smax[0 * N_ + n] = m0; g_ssum[0 * N_ + n] = s0;
            g_smax[1 * N_ + n] = m1; g_ssum[1 * N_ + n] = s1;
            g_smax[2 * N_ + n] = m2; g_ssum[2 * N_ + n] = s2;
            g_smax[3 * N_ + n] = m3; g_ssum[3 * N_ + n] = s3;
        }
    }
}

// ---------- initial mean features: 1 warp/node, lane=float4, 2-edge ILP ---------
__global__ void __launch_bounds__(256) init_kernel(const float* __restrict__ ent,
                                                   const float* __restrict__ rel, int N_) {
    int w = (blockIdx.x * blockDim.x + threadIdx.x) >> 5;
    if (w >= N_) return;
    int lane = threadIdx.x & 31;
    int s = g_rowptr[w], e = g_rowptr[w + 1];
    float4 ae = make_float4(0, 0, 0, 0), ar = make_float4(0, 0, 0, 0);
    int i = s;
    for (; i + 1 < e; i += 2) {
        int2 e0 = g_edge[i], e1 = g_edge[i + 1];
        float4 a = *(const float4*)(ent + (size_t)e0.x * FF + lane * 4);
        float4 b = *(const float4*)(rel + (size_t)e0.y * FF + lane * 4);
        float4 c = *(const float4*)(ent + (size_t)e1.x * FF + lane * 4);
        float4 d = *(const float4*)(rel + (size_t)e1.y * FF + lane * 4);
        ae.x += a.x + c.x; ae.y += a.y + c.y; ae.z += a.z + c.z; ae.w += a.w + c.w;
        ar.x += b.x + d.x; ar.y += b.y + d.y; ar.z += b.z + d.z; ar.w += b.w + d.w;
    }
    if (i < e) {
        int2 e0 = g_edge[i];
        float4 a = *(const float4*)(ent + (size_t)e0.x * FF + lane * 4);
        float4 b = *(const float4*)(rel + (size_t)e0.y * FF + lane * 4);
        ae.x += a.x; ae.y += a.y; ae.z += a.z; ae.w += a.w;
        ar.x += b.x; ar.y += b.y; ar.z += b.z; ar.w += b.w;
    }
    float inv = 1.f / fmaxf((float)(e - s), 1.f);
    float* oe = &g_out[0][(size_t)w * FD + lane * 4];
    float* orr = &g_out[1][(size_t)w * FD + lane * 4];
    oe[0] = tanhf(ae.x * inv); oe[1] = tanhf(ae.y * inv);
    oe[2] = tanhf(ae.z * inv); oe[3] = tanhf(ae.w * inv);
    orr[0] = tanhf(ar.x * inv); orr[1] = tanhf(ar.y * inv);
    orr[2] = tanhf(ar.z * inv); orr[3] = tanhf(ar.w * inv);
}

// ---------- GNN layer: 1 warp/node, lane=float4 (coalesced), 4-edge ILP ---------
__global__ void __launch_bounds__(256) layer_kernel(int layer, int N_, int R_) {
    int gw = (blockIdx.x * blockDim.x + threadIdx.x) >> 5;
    if (gw >= 2 * N_) return;
    int dual = gw >= N_;
    int w = gw - dual * N_;
    int lane = threadIdx.x & 31;
    int s = g_rowptr[w], e = g_rowptr[w + 1];
    int t = dual * 2 + layer;
    const float* feats = g_out[dual];
    const float* tt = g_ttab + (size_t)t * R_;
    float smax = g_smax[(size_t)t * N_ + w];
    float invs = (e > s) ? 1.f / g_ssum[(size_t)t * N_ + w] : 0.f;
    int coff = layer * FF + lane * 4;
    float4 acc = make_float4(0, 0, 0, 0);

    for (int i = s; i < e; i += 4) {
        int i1 = min(i + 1, e - 1), i2 = min(i + 2, e - 1), i3 = min(i + 3, e - 1);
        float a1 = (i + 1 < e) ? 1.f : 0.f;
        float a2 = (i + 2 < e) ? 1.f : 0.f;
        float a3 = (i + 3 < e) ? 1.f : 0.f;
        int2 e0 = g_edge[i], e1 = g_edge[i1], e2 = g_edge[i2], e3 = g_edge[i3];
        float4 f0 = *(const float4*)(feats + (size_t)e0.x * FD + coff);
        float4 f1 = *(const float4*)(feats + (size_t)e1.x * FD + coff);
        float4 f2 = *(const float4*)(feats + (size_t)e2.x * FD + coff);
        float4 f3 = *(const float4*)(feats + (size_t)e3.x * FD + coff);
        float4 r0 = *(const float4*)(g_relnorm + (size_t)e0.y * FF + lane * 4);
        float4 r1 = *(const float4*)(g_relnorm + (size_t)e1.y * FF + lane * 4);
        float4 r2 = *(const float4*)(g_relnorm + (size_t)e2.y * FF + lane * 4);
        float4 r3 = *(const float4*)(g_relnorm + (size_t)e3.y * FF + lane * 4);
        float p0 = f0.x * r0.x + f0.y * r0.y + f0.z * r0.z + f0.w * r0.w;
        float p1 = f1.x * r1.x + f1.y * r1.y + f1.z * r1.z + f1.w * r1.w;
        float p2 = f2.x * r2.x + f2.y * r2.y + f2.z * r2.z + f2.w * r2.w;
        float p3 = f3.x * r3.x + f3.y * r3.y + f3.z * r3.z + f3.w * r3.w;
#pragma unroll
        for (int o = 16; o; o >>= 1) {
            p0 += __shfl_xor_sync(0xffffffffu, p0, o);
            p1 += __shfl_xor_sync(0xffffffffu, p1, o);
            p2 += __shfl_xor_sync(0xffffffffu, p2, o);
            p3 += __shfl_xor_sync(0xffffffffu, p3, o);
        }
        float w0 = __expf(tt[e0.y] - smax) * invs;
        float w1 = __expf(tt[e1.y] - smax) * invs * a1;
        float w2 = __expf(tt[e2.y] - smax) * invs * a2;
        float w3 = __expf(tt[e3.y] - smax) * invs * a3;
        float c0 = 2.f * p0 * w0, c1 = 2.f * p1 * w1;
        float c2 = 2.f * p2 * w2, c3 = 2.f * p3 * w3;
        acc.x += w0 * f0.x - c0 * r0.x + w1 * f1.x - c1 * r1.x
               + w2 * f2.x - c2 * r2.x + w3 * f3.x - c3 * r3.x;
        acc.y += w0 * f0.y - c0 * r0.y + w1 * f1.y - c1 * r1.y
               + w2 * f2.y - c2 * r2.y + w3 * f3.y - c3 * r3.y;
        acc.z += w0 * f0.z - c0 * r0.z + w1 * f1.z - c1 * r1.z
               + w2 * f2.z - c2 * r2.z + w3 * f3.z - c3 * r3.z;
        acc.w += w0 * f0.w - c0 * r0.w + w1 * f1.w - c1 * r1.w
               + w2 * f2.w - c2 * r2.w + w3 * f3.w - c3 * r3.w;
    }
    float* o = &g_out[dual][(size_t)w * FD + (layer + 1) * FF + lane * 4];
    o[0] = tanhf(acc.x); o[1] = tanhf(acc.y);
    o[2] = tanhf(acc.z); o[3] = tanhf(acc.w);
}

// --------- proxy normalization: write normalized + raw bf16 hi/lo ---------------
__global__ void pnorm_kernel(const float* __restrict__ pe, const float* __restrict__ pr) {
    int w = (blockIdx.x * blockDim.x + threadIdx.x) >> 5;
    if (w >= 2 * PP) return;
    int lane = threadIdx.x & 31;
    int dual = (w >= PP) ? 1 : 0;
    int row = w & (PP - 1);
    const float* p = dual ? pr : pe;
    float v[12];
    float ss = 0;
#pragma unroll
    for (int j = 0; j < 12; j++) {
        v[j] = p[(size_t)row * FD + lane + 32 * j];
        ss += v[j] * v[j];
    }
    ss = wsum(ss);
    float inv = 1.f / fmaxf(sqrtf(ss), EPSV);
#pragma unroll
    for (int j = 0; j < 12; j++) {
        int idx = row * FD + lane + 32 * j;
        __nv_bfloat16 h, l;
        split_bf16(v[j] * inv, h, l);
        g_pnh[dual][idx] = h; g_pnl[dual][idx] = l;
        split_bf16(v[j], h, l);
        g_ph[dual][idx] = h; g_pl[dual][idx] = l;
    }
}

// ------------------------ W -> bf16 hi/lo split ---------------------------------
__global__ void wconv_kernel(const float* __restrict__ We, const float* __restrict__ Wr) {
    int i = blockIdx.x * blockDim.x + threadIdx.x;
    if (i >= 2 * FD * FD) return;
    int dual = i >= FD * FD;
    int j = i - dual * FD * FD;
    float v = (dual ? Wr : We)[j];
    __nv_bfloat16 h, l;
    split_bf16(v, h, l);
    g_wh[dual][j] = h;
    g_wl[dual][j] = l;
}

#define ALD 40
#define SLD 68
#define BLD 72

// ------- S = l2norm(O) @ Pn^T (WMMA 3-term, in-kernel O conversion) -------------
// Each thread owns (row=tid>>1, half=tid&1): loads 16 fp32 O values per K-step,
// splits to bf16 hi/lo in smem, accumulates exact fp32 sumsq on the side.
__global__ void __launch_bounds__(256) s_wmma_kernel(int N_) {
    __shared__ __align__(16) char smraw[34816];
    __shared__ float ssqp[128][2];
    __nv_bfloat16* Ah = (__nv_bfloat16*)smraw;           // [128][ALD]
    __nv_bfloat16* Al = Ah + 128 * ALD;
    __nv_bfloat16* Bh = Al + 128 * ALD;                  // [64][ALD]
    __nv_bfloat16* Bl = Bh + 64 * ALD;
    float* stage = (float*)smraw;                        // [128][SLD]

    int tid = threadIdx.x, wid = tid >> 5, lane = tid & 31;
    int warpM = wid & 3, warpN = wid >> 2;
    int rowBase = blockIdx.x * 128;
    int dual = blockIdx.z;
    const float* O = g_out[dual];
    const unsigned* PNH = (const unsigned*)g_pnh[dual];
    const unsigned* PNL = (const unsigned*)g_pnl[dual];

    int arow = tid >> 1, ahalf = tid & 1;
    int agr = rowBase + arow;
    const float* aptr = O + (size_t)agr * FD + ahalf * 16;
    float myssq = 0.f;

    wmma::fragment<wmma::accumulator, 16, 16, 16, float> c[2][2];
#pragma unroll
    for (int i = 0; i < 2; i++)
#pragma unroll
        for (int j = 0; j < 2; j++) wmma::fill_fragment(c[i][j], 0.f);

    for (int k0 = 0; k0 < FD; k0 += 32) {
        // A: load fp32 O, split to hi/lo bf16 in smem
        {
            float v[16];
            if (agr < N_) {
#pragma unroll
                for (int q = 0; q < 4; q++)
                    *(float4*)(&v[q * 4]) = *(const float4*)(aptr + k0 + q * 4);
            } else {
#pragma unroll
                for (int j = 0; j < 16; j++) v[j] = 0.f;
            }
            __nv_bfloat162* dh = (__nv_bfloat162*)(Ah + arow * ALD) + ahalf * 8;
            __nv_bfloat162* dl = (__nv_bfloat162*)(Al + arow * ALD) + ahalf * 8;
#pragma unroll
            for (int j = 0; j < 8; j++) {
                __nv_bfloat16 h0, l0, h1, l1;
                split_bf16(v[2 * j], h0, l0);
                split_bf16(v[2 * j + 1], h1, l1);
                dh[j] = __nv_bfloat162(h0, h1);
                dl[j] = __nv_bfloat162(l0, l1);
                myssq = fmaf(v[2 * j], v[2 * j], myssq);
                myssq = fmaf(v[2 * j + 1], v[2 * j + 1], myssq);
            }
        }
        // B: Pn bf16 hi/lo, [64 rows][32 k] = 1024 uints each
        for (int s = tid; s < 1024; s += 256) {
            int br = s >> 4, cu = s & 15;
            size_t gi = ((size_t)br * FD + k0) / 2 + cu;
            ((unsigned*)(Bh + br * ALD))[cu] = PNH[gi];
            ((unsigned*)(Bl + br * ALD))[cu] = PNL[gi];
        }
        __syncthreads();
#pragma unroll
        for (int ks = 0; ks < 32; ks += 16) {
            wmma::fragment<wmma::matrix_a, 16, 16, 16, __nv_bfloat16, wmma::row_major> a[2];
            wmma::fragment<wmma::matrix_b, 16, 16, 16, __nv_bfloat16, wmma::col_major> b[2];
#pragma unroll
            for (int i = 0; i < 2; i++)
                wmma::load_matrix_sync(a[i], Ah + (warpM * 32 + i * 16) * ALD + ks, ALD);
#pragma unroll
            for (int j = 0; j < 2; j++)
                wmma::load_matrix_sync(b[j], Bh + (warpN * 32 + j * 16) * ALD + ks, ALD);
#pragma unroll
            for (int i = 0; i < 2; i++)
#pragma unroll
                for (int j = 0; j < 2; j++) wmma::mma_sync(c[i][j], a[i], b[j], c[i][j]);
#pragma unroll
            for (int i = 0; i < 2; i++)
                wmma::load_matrix_sync(a[i], Al + (warpM * 32 + i * 16) * ALD + ks, ALD);
#pragma unroll
            for (int i = 0; i < 2; i++)
#pragma unroll
                for (int j = 0; j < 2; j++) wmma::mma_sync(c[i][j], a[i], b[j], c[i][j]);
#pragma unroll
            for (int i = 0; i < 2; i++)
                wmma::load_matrix_sync(a[i], Ah + (warpM * 32 + i * 16) * ALD + ks, ALD);
#pragma unroll
            for (int j = 0; j < 2; j++)
                wmma::load_matrix_sync(b[j], Bl + (warpN * 32 + j * 16) * ALD + ks, ALD);
#pragma unroll
            for (int i = 0; i < 2; i++)
#pragma unroll
                for (int j = 0; j < 2; j++) wmma::mma_sync(c[i][j], a[i], b[j], c[i][j]);
        }
        __syncthreads();
    }
    ssqp[arow][ahalf] = myssq;

#pragma unroll
    for (int i = 0; i < 2; i++)
#pragma unroll
        for (int j = 0; j < 2; j++)
            wmma::store_matrix_sync(stage + (warpM * 32 + i * 16) * SLD + warpN * 32 + j * 16,
                                    c[i][j], SLD, wmma::mem_row_major);
    __syncthreads();

    // fused: scale by 1/||O||, softmax over 64 proxies, write att bf16 hi/lo
    __nv_bfloat162* ATTH = (__nv_bfloat162*)g_atth[dual];
    __nv_bfloat162* ATTL = (__nv_bfloat162*)g_attl[dual];
#pragma unroll
    for (int i = 0; i < 16; i++) {
        int r = wid * 16 + i;
        int n = rowBase + r;
        float inv = 0.f;
        if (n < N_) inv = 1.f / fmaxf(sqrtf(ssqp[r][0] + ssqp[r][1]), EPSV);
        float v0 = stage[r * SLD + lane * 2] * inv;
        float v1 = stage[r * SLD + lane * 2 + 1] * inv;
        float m = fmaxf(v0, v1);
#pragma unroll
        for (int o = 16; o; o >>= 1) m = fmaxf(m, __shfl_xor_sync(0xffffffffu, m, o));
        float e0 = __expf(v0 - m), e1 = __expf(v1 - m);
        float sm = e0 + e1;
#pragma unroll
        for (int o = 16; o; o >>= 1) sm += __shfl_xor_sync(0xffffffffu, sm, o);
        float rc = 1.f / sm;
        if (n < N_) {
            float a0 = e0 * rc, a1 = e1 * rc;
            __nv_bfloat16 h0, l0, h1, l1;
            split_bf16(a0, h0, l0);
            split_bf16(a1, h1, l1);
            size_t bi = ((size_t)n * PP + lane * 2) >> 1;
            ATTH[bi] = __nv_bfloat162(h0, h1);
            ATTL[bi] = __nv_bfloat162(l0, l1);
        }
    }
}

// ------- PF = O - Att @ P (WMMA 3-term, K=64) -> bf16 hi/lo ---------------------
__global__ void __launch_bounds__(256) pf_wmma_kernel(int N_) {
    __shared__ __align__(16) char smraw[34816];
    __nv_bfloat16* Ah = (__nv_bfloat16*)smraw;           // [128][ALD]
    __nv_bfloat16* Al = Ah + 128 * ALD;
    __nv_bfloat16* Bh = Al + 128 * ALD;                  // [32 k][BLD cols]
    __nv_bfloat16* Bl = Bh + 32 * BLD;
    float* stage = (float*)smraw;                        // [128][SLD]

    int tid = threadIdx.x, wid = tid >> 5, lane = tid & 31;
    int warpM = wid & 3, warpN = wid >> 2;
    int colBase = blockIdx.x * 64;
    int rowBase = blockIdx.y * 128;
    int dual = blockIdx.z;
    const unsigned* ATH = (const unsigned*)g_atth[dual];
    const unsigned* ATL = (const unsigned*)g_attl[dual];
    const unsigned* PH = (const unsigned*)g_ph[dual];
    const unsigned* PL = (const unsigned*)g_pl[dual];

    wmma::fragment<wmma::accumulator, 16, 16, 16, float> c[2][2];
#pragma unroll
    for (int i = 0; i < 2; i++)
#pragma unroll
        for (int j = 0; j < 2; j++) wmma::fill_fragment(c[i][j], 0.f);

    for (int k0 = 0; k0 < PP; k0 += 32) {
        for (int s = tid; s < 2048; s += 256) {
            int r = s >> 4, cu = s & 15;
            int gr = rowBase + r;
            unsigned vh = 0, vl = 0;
            if (gr < N_) {
                size_t gi = ((size_t)gr * PP + k0) / 2 + cu;
                vh = ATH[gi]; vl = ATL[gi];
            }
            ((unsigned*)(Ah + r * ALD))[cu] = vh;
            ((unsigned*)(Al + r * ALD))[cu] = vl;
        }
        for (int s = tid; s < 1024; s += 256) {
            int k = s >> 5, cp = s & 31;
            size_t gi = ((size_t)(k0 + k) * FD + colBase) / 2 + cp;
            ((unsigned*)(Bh + k * BLD))[cp] = PH[gi];
            ((unsigned*)(Bl + k * BLD))[cp] = PL[gi];
        }
        __syncthreads();
#pragma unroll
        for (int ks = 0; ks < 32; ks += 16) {
            wmma::fragment<wmma::matrix_a, 16, 16, 16, __nv_bfloat16, wmma::row_major> a[2];
            wmma::fragment<wmma::matrix_b, 16, 16, 16, __nv_bfloat16, wmma::row_major> b[2];
#pragma unroll
            for (int i = 0; i < 2; i++)
                wmma::load_matrix_sync(a[i], Ah + (warpM * 32 + i * 16) * ALD + ks, ALD);
#pragma unroll
            for (int j = 0; j < 2; j++)
                wmma::load_matrix_sync(b[j], Bh + ks * BLD + warpN * 32 + j * 16, BLD);
#pragma unroll
            for (int i = 0; i < 2; i++)
#pragma unroll
                for (int j = 0; j < 2; j++) wmma::mma_sync(c[i][j], a[i], b[j], c[i][j]);
#pragma unroll
            for (int i = 0; i < 2; i++)
                wmma::load_matrix_sync(a[i], Al + (warpM * 32 + i * 16) * ALD + ks, ALD);
#pragma unroll
            for (int i = 0; i < 2; i++)
#pragma unroll
                for (int j = 0; j < 2; j++) wmma::mma_sync(c[i][j], a[i], b[j], c[i][j]);
#pragma unroll
            for (int i = 0; i < 2; i++)
                wmma::load_matrix_sync(a[i], Ah + (warpM * 32 + i * 16) * ALD + ks, ALD);
#pragma unroll
            for (int j = 0; j < 2; j++)
                wmma::load_matrix_sync(b[j], Bl + ks * BLD + warpN * 32 + j * 16, BLD);
#pragma unroll
            for (int i = 0; i < 2; i++)
#pragma unroll
                for (int j = 0; j < 2; j++) wmma::mma_sync(c[i][j], a[i], b[j], c[i][j]);
        }
        __syncthreads();
    }

#pragma unroll
    for (int i = 0; i < 2; i++)
#pragma unroll
        for (int j = 0; j < 2; j++)
            wmma::store_matrix_sync(stage + (warpM * 32 + i * 16) * SLD + warpN * 32 + j * 16,
                                    c[i][j], SLD, wmma::mem_row_major);
    __syncthreads();

    const float* O = g_out[dual];
    __nv_bfloat162* DH = (__nv_bfloat162*)g_pfh[dual];
    __nv_bfloat162* DL = (__nv_bfloat162*)g_pfl[dual];
#pragma unroll
    for (int i = 0; i < 16; i++) {
        int r = wid * 16 + i;
        int n = rowBase + r;
        if (n >= N_) continue;
        int c0 = colBase + lane * 2;
        float2 acc = *(float2*)(stage + r * SLD + lane * 2);
        float2 ov = *(const float2*)(O + (size_t)n * FD + c0);
        float va = ov.x - acc.x;
        float vb = ov.y - acc.y;
        __nv_bfloat16 ha, la, hb, lb;
        split_bf16(va, ha, la);
        split_bf16(vb, hb, lb);
        size_t bi = ((size_t)n * FD + c0) >> 1;
        DH[bi] = __nv_bfloat162(ha, hb);
        DL[bi] = __nv_bfloat162(la, lb);
    }
}

// ------- F2: WMMA bf16 3-term split GEMM + sigmoid blend ------------------------
__global__ void __launch_bounds__(256) f2_wmma_kernel(const float* __restrict__ be,
                                                      const float* __restrict__ br,
                                                      float* __restrict__ out, int N_) {
    __shared__ __align__(16) char smraw[34816];
    __nv_bfloat16* Ah = (__nv_bfloat16*)smraw;           // [128][ALD]
    __nv_bfloat16* Al = Ah + 128 * ALD;
    __nv_bfloat16* Bh = Al + 128 * ALD;                  // [64][ALD] (n-major, k inner)
    __nv_bfloat16* Bl = Bh + 64 * ALD;
    float* stage = (float*)smraw;                        // [128][SLD]

    int tid = threadIdx.x, wid = tid >> 5, lane = tid & 31;
    int warpM = wid & 3, warpN = wid >> 2;
    int colBase = blockIdx.x * 64;
    int rowBase = blockIdx.y * 128;
    int dual = blockIdx.z;
    const float* bias = dual ? br : be;
    const __nv_bfloat16* PH = g_pfh[dual];
    const __nv_bfloat16* PL = g_pfl[dual];
    const __nv_bfloat16* WH = g_wh[dual];
    const __nv_bfloat16* WL = g_wl[dual];

    wmma::fragment<wmma::accumulator, 16, 16, 16, float> c[2][2];
#pragma unroll
    for (int i = 0; i < 2; i++)
#pragma unroll
        for (int j = 0; j < 2; j++) wmma::fill_fragment(c[i][j], 0.f);

    for (int k0 = 0; k0 < FD; k0 += 32) {
        for (int s = tid; s < 2048; s += 256) {
            int r = s >> 4, cu = s & 15;
            int gr = rowBase + r;
            unsigned vh = 0, vl = 0;
            if (gr < N_) {
                size_t gi = ((size_t)gr * FD + k0) / 2 + cu;
                vh = ((const unsigned*)PH)[gi];
                vl = ((const unsigned*)PL)[gi];
            }
            ((unsigned*)(Ah + r * ALD))[cu] = vh;
            ((unsigned*)(Al + r * ALD))[cu] = vl;
        }
        for (int s = tid; s < 64 * 32; s += 256) {
            int n = s & 63, k = s >> 6;
            size_t gi = (size_t)(k0 + k) * FD + colBase + n;
            Bh[n * ALD + k] = WH[gi];
            Bl[n * ALD + k] = WL[gi];
        }
        __syncthreads();
#pragma unroll
        for (int ks = 0; ks < 32; ks += 16) {
            wmma::fragment<wmma::matrix_a, 16, 16, 16, __nv_bfloat16, wmma::row_major> a[2];
            wmma::fragment<wmma::matrix_b, 16, 16, 16, __nv_bfloat16, wmma::col_major> b[2];
#pragma unroll
            for (int i = 0; i < 2; i++)
                wmma::load_matrix_sync(a[i], Ah + (warpM * 32 + i * 16) * ALD + ks, ALD);
#pragma unroll
            for (int j = 0; j < 2; j++)
                wmma::load_matrix_sync(b[j], Bh + (warpN * 32 + j * 16) * ALD + ks, ALD);
#pragma unroll
            for (int i = 0; i < 2; i++)
#pragma unroll
                for (int j = 0; j < 2; j++) wmma::mma_sync(c[i][j], a[i], b[j], c[i][j]);
#pragma unroll
            for (int i = 0; i < 2; i++)
                wmma::load_matrix_sync(a[i], Al + (warpM * 32 + i * 16) * ALD + ks, ALD);
#pragma unroll
            for (int i = 0; i < 2; i++)
#pragma unroll
                for (int j = 0; j < 2; j++) wmma::mma_sync(c[i][j], a[i], b[j], c[i][j]);
#pragma unroll
            for (int i = 0; i < 2; i++)
                wmma::load_matrix_sync(a[i], Ah + (warpM * 32 + i * 16) * ALD + ks, ALD);
#pragma unroll
            for (int j = 0; j < 2; j++)
                wmma::load_matrix_sync(b[j], Bl + (warpN * 32 + j * 16) * ALD + ks, ALD);
#pragma unroll
            for (int i = 0; i < 2; i++)
#pragma unroll
                for (int j = 0; j < 2; j++) wmma::mma_sync(c[i][j], a[i], b[j], c[i][j]);
        }
        __syncthreads();
    }

#pragma unroll
    for (int i = 0; i < 2; i++)
#pragma unroll
        for (int j = 0; j < 2; j++)
            wmma::store_matrix_sync(stage + (warpM * 32 + i * 16) * SLD + warpN * 32 + j * 16,
                                    c[i][j], SLD, wmma::mem_row_major);
    __syncthreads();

    const float* O = g_out[dual];
    const __nv_bfloat162* PH2 = (const __nv_bfloat162*)PH;
    const __nv_bfloat162* PL2 = (const __nv_bfloat162*)PL;
#pragma unroll
    for (int i = 0; i < 16; i++) {
        int r = wid * 16 + i;
        int n = rowBase + r;
        if (n >= N_) continue;
        int c0 = colBase + lane * 2;
        float2 acc = *(float2*)(stage + r * SLD + lane * 2);
        float2 bv = *(const float2*)(bias + c0);
        float2 ov = *(const float2*)(O + (size_t)n * FD + c0);
        size_t pi = ((size_t)n * FD + c0) >> 1;
        __nv_bfloat162 h0 = PH2[pi];
        __nv_bfloat162 l0 = PL2[pi];
        float pf0 = __bfloat162float(h0.x) + __bfloat162float(l0.x);
        float pf1 = __bfloat162float(h0.y) + __bfloat162float(l0.y);
        float g0 = 1.f / (1.f + __expf(-(acc.x + bv.x)));
        float g1 = 1.f / (1.f + __expf(-(acc.y + bv.y)));
        float2 res;
        res.x = g0 * ov.x + (1.f - g0) * pf0;
        res.y = g1 * ov.y + (1.f - g1) * pf1;
        *(float2*)(out + (size_t)n * (2 * FD) + dual * FD + c0) = res;
    }
}

// ------------------------ launch ------------------------------------------------
extern "C" void kernel_launch(void* const* d_in, const int* in_sizes, int n_in,
                              void* d_out, int out_size) {
    const float* ent_emb = (const float*)d_in[0];
    const float* rel_emb = (const float*)d_in[1];
    const int* edge_src  = (const int*)d_in[2];
    const int* edge_dst  = (const int*)d_in[3];
    const int* edge_rel  = (const int*)d_in[4];
    const float* attn_e  = (const float*)d_in[5];
    const float* gate_e  = (const float*)d_in[6];
    const float* proxy_e = (const float*)d_in[7];
    const float* bias_e  = (const float*)d_in[8];
    const float* attn_r  = (const float*)d_in[9];
    const float* gate_r  = (const float*)d_in[10];
    const float* proxy_r = (const float*)d_in[11];
    const float* bias_r  = (const float*)d_in[12];

    int N_ = in_sizes[0] / FF;
    int R_ = in_sizes[1] / FF;
    int E_ = in_sizes[2];
    float* out = (float*)d_out;

    zero_deg_kernel<<<(N_ + 255) / 256, 256>>>(N_);
    count_kernel<<<(E_ + 255) / 256, 256>>>(edge_dst, E_);
    scan_kernel<<<1, 1024>>>(N_);
    scatter_kernel<<<(E_ + 255) / 256, 256>>>(edge_dst, edge_src, edge_rel, E_);
    relnorm_kernel<<<(R_ * 32 + 255) / 256, 256>>>(rel_emb, attn_e, attn_r, R_);
    stats_kernel<<<1184, 256>>>(N_, R_);
    init_kernel<<<(N_ * 32 + 255) / 256, 256>>>(ent_emb, rel_emb, N_);
    wconv_kernel<<<(2 * FD * FD + 255) / 256, 256>>>(gate_e, gate_r);
    pnorm_kernel<<<16, 256>>>(proxy_e, proxy_r);

    int lgrid = (2 * N_ * 32 + 255) / 256;
    layer_kernel<<<lgrid, 256>>>(0, N_, R_);
    layer_kernel<<<lgrid, 256>>>(1, N_, R_);

    int rb = (N_ + 127) / 128;
    dim3 gs(rb, 1, 2);
    s_wmma_kernel<<<gs, 256>>>(N_);

    dim3 gpf(FD / 64, rb, 2);
    pf_wmma_kernel<<<gpf, 256>>>(N_);

    dim3 g2(FD / 64, rb, 2);
    f2_wmma_kernel<<<g2, 256>>>(bias_e, bias_r, out, N_);
}

// round 12
// speedup vs baseline: 1.1685x; 1.0692x over previous
#include <cuda_runtime.h>
#include <cuda_bf16.h>
#include <mma.h>
#include <stdint.h>
#include <math.h>

using namespace nvcuda;

#define MAXN 50000
#define MAXE 800000
#define MAXR 2000
#define FF   128
#define FD   384
#define PP   64
#define EPSV 1e-12f

// ------------------------ scratch (device globals, no allocs) ------------------
__device__ int   g_deg[MAXN];
__device__ int   g_rowptr[MAXN + 1];
__device__ int   g_cursor[MAXN];
__device__ int2  g_edge[MAXE];                  // (src, rel) in CSR-by-dst order
__device__ float g_relnorm[MAXR * FF];
__device__ float g_ttab[4 * MAXR];
__device__ float g_smax[4 * MAXN];
__device__ float g_ssum[4 * MAXN];
__device__ float g_out[2][(size_t)MAXN * FD];   // fp32 concat features
__device__ __nv_bfloat16 g_pnh[2][PP * FD];            // l2norm proxy hi
__device__ __nv_bfloat16 g_pnl[2][PP * FD];            // l2norm proxy lo
__device__ __nv_bfloat16 g_ph[2][PP * FD];             // raw proxy hi
__device__ __nv_bfloat16 g_pl[2][PP * FD];             // raw proxy lo
__device__ __nv_bfloat16 g_atth[2][(size_t)MAXN * PP]; // attention hi
__device__ __nv_bfloat16 g_attl[2][(size_t)MAXN * PP]; // attention lo
__device__ __nv_bfloat16 g_pfh[2][(size_t)MAXN * FD];  // proxy_feature hi
__device__ __nv_bfloat16 g_pfl[2][(size_t)MAXN * FD];  // proxy_feature lo
__device__ __nv_bfloat16 g_wh[2][FD * FD];             // gate kernel hi
__device__ __nv_bfloat16 g_wl[2][FD * FD];             // gate kernel lo

__device__ __forceinline__ float wsum(float v) {
#pragma unroll
    for (int o = 16; o; o >>= 1) v += __shfl_xor_sync(0xffffffffu, v, o);
    return v;
}
__device__ __forceinline__ float wmax(float v) {
#pragma unroll
    for (int o = 16; o; o >>= 1) v = fmaxf(v, __shfl_xor_sync(0xffffffffu, v, o));
    return v;
}
__device__ __forceinline__ void split_bf16(float v, __nv_bfloat16& h, __nv_bfloat16& l) {
    h = __float2bfloat16(v);
    l = __float2bfloat16(v - __bfloat162float(h));
}

// ------------------------ CSR build ------------------------
__global__ void zero_deg_kernel(int N_) {
    int i = blockIdx.x * blockDim.x + threadIdx.x;
    if (i < N_) g_deg[i] = 0;
}

__global__ void count_kernel(const int* __restrict__ edst, int E_) {
    int e = blockIdx.x * blockDim.x + threadIdx.x;
    if (e < E_) atomicAdd(&g_deg[edst[e]], 1);
}

__global__ void scan_kernel(int N_) {
    __shared__ int sh[1024];
    __shared__ int carry;
    if (threadIdx.x == 0) carry = 0;
    __syncthreads();
    for (int base = 0; base < N_; base += 1024) {
        int i = base + threadIdx.x;
        int v = (i < N_) ? g_deg[i] : 0;
        sh[threadIdx.x] = v;
        __syncthreads();
#pragma unroll
        for (int off = 1; off < 1024; off <<= 1) {
            int t = (threadIdx.x >= off) ? sh[threadIdx.x - off] : 0;
            __syncthreads();
            sh[threadIdx.x] += t;
            __syncthreads();
        }
        int inc = sh[threadIdx.x];
        int exc = inc - v + carry;
        if (i < N_) { g_rowptr[i] = exc; g_cursor[i] = exc; }
        __syncthreads();
        if (threadIdx.x == 1023) carry += sh[1023];
        __syncthreads();
    }
    if (threadIdx.x == 0) g_rowptr[N_] = carry;
}

__global__ void scatter_kernel(const int* __restrict__ edst,
                               const int* __restrict__ esrc,
                               const int* __restrict__ erel, int E_) {
    int e = blockIdx.x * blockDim.x + threadIdx.x;
    if (e < E_) {
        int p = atomicAdd(&g_cursor[edst[e]], 1);
        g_edge[p] = make_int2(esrc[e], erel[e]);
    }
}

// ------------------------ relation normalization + attn tables ------------------
__global__ void relnorm_kernel(const float* __restrict__ rel,
                               const float* __restrict__ attn_e,
                               const float* __restrict__ attn_r, int R_) {
    int w = (blockIdx.x * blockDim.x + threadIdx.x) >> 5;
    int lane = threadIdx.x & 31;
    if (w >= R_) return;
    float4 v = *(const float4*)(rel + (size_t)w * FF + lane * 4);
    float ss = v.x * v.x + v.y * v.y + v.z * v.z + v.w * v.w;
    ss = wsum(ss);
    float inv = 1.f / fmaxf(sqrtf(ss), EPSV);
    float4 rn = make_float4(v.x * inv, v.y * inv, v.z * inv, v.w * inv);
    *(float4*)(g_relnorm + (size_t)w * FF + lane * 4) = rn;

    float4 a0 = *(const float4*)(attn_e + lane * 4);
    float4 a1 = *(const float4*)(attn_e + FF + lane * 4);
    float4 a2 = *(const float4*)(attn_r + lane * 4);
    float4 a3 = *(const float4*)(attn_r + FF + lane * 4);
    float d0 = wsum(rn.x * a0.x + rn.y * a0.y + rn.z * a0.z + rn.w * a0.w);
    float d1 = wsum(rn.x * a1.x + rn.y * a1.y + rn.z * a1.z + rn.w * a1.w);
    float d2 = wsum(rn.x * a2.x + rn.y * a2.y + rn.z * a2.z + rn.w * a2.w);
    float d3 = wsum(rn.x * a3.x + rn.y * a3.y + rn.z * a3.z + rn.w * a3.w);
    if (lane == 0) {
        g_ttab[0 * R_ + w] = d0;
        g_ttab[1 * R_ + w] = d1;
        g_ttab[2 * R_ + w] = d2;
        g_ttab[3 * R_ + w] = d3;
    }
}

// ------------------------ edge-softmax stats (all 4 tables at once) -------------
__global__ void __launch_bounds__(256) stats_kernel(int N_, int R_) {
    __shared__ float tab[4 * MAXR];
    int tid = threadIdx.x;
    for (int i = tid; i < 4 * R_; i += blockDim.x) tab[i] = g_ttab[i];
    __syncthreads();
    int warp = tid >> 5, lane = tid & 31;
    for (int n = blockIdx.x * 8 + warp; n < N_; n += gridDim.x * 8) {
        int s = g_rowptr[n], e = g_rowptr[n + 1];
        float m0 = -1e30f, m1 = -1e30f, m2 = -1e30f, m3 = -1e30f;
        for (int i = s + lane; i < e; i += 32) {
            int r = g_edge[i].y;
            m0 = fmaxf(m0, tab[r]);
            m1 = fmaxf(m1, tab[R_ + r]);
            m2 = fmaxf(m2, tab[2 * R_ + r]);
            m3 = fmaxf(m3, tab[3 * R_ + r]);
        }
        m0 = wmax(m0); m1 = wmax(m1); m2 = wmax(m2); m3 = wmax(m3);
        float s0 = 0, s1 = 0, s2 = 0, s3 = 0;
        for (int i = s + lane; i < e; i += 32) {
            int r = g_edge[i].y;
            s0 += __expf(tab[r] - m0);
            s1 += __expf(tab[R_ + r] - m1);
            s2 += __expf(tab[2 * R_ + r] - m2);
            s3 += __expf(tab[3 * R_ + r] - m3);
        }
        s0 = wsum(s0); s1 = wsum(s1); s2 = wsum(s2); s3 = wsum(s3);
        if (lane == 0) {
            g_smax[0 * N_ + n] = m0; g_ssum[0 * N_ + n] = s0;
            g_smax[1 * N_ + n] = m1; g_ssum[1 * N_ + n] = s1;
            g_smax[2 * N_ + n] = m2; g_ssum[2 * N_ + n] = s2;
            g_smax[3 * N_ + n] = m3; g_ssum[3 * N_ + n] = s3;
        }
    }
}

// ---------- initial mean features: 1 warp/node, lane=float4, 2-edge ILP ---------
__global__ void __launch_bounds__(256) init_kernel(const float* __restrict__ ent,
                                                   const float* __restrict__ rel, int N_) {
    int w = (blockIdx.x * blockDim.x + threadIdx.x) >> 5;
    if (w >= N_) return;
    int lane = threadIdx.x & 31;
    int s = g_rowptr[w], e = g_rowptr[w + 1];
    float4 ae = make_float4(0, 0, 0, 0), ar = make_float4(0, 0, 0, 0);
    int i = s;
    for (; i + 1 < e; i += 2) {
        int2 e0 = g_edge[i], e1 = g_edge[i + 1];
        float4 a = *(const float4*)(ent + (size_t)e0.x * FF + lane * 4);
        float4 b = *(const float4*)(rel + (size_t)e0.y * FF + lane * 4);
        float4 c = *(const float4*)(ent + (size_t)e1.x * FF + lane * 4);
        float4 d = *(const float4*)(rel + (size_t)e1.y * FF + lane * 4);
        ae.x += a.x + c.x; ae.y += a.y + c.y; ae.z += a.z + c.z; ae.w += a.w + c.w;
        ar.x += b.x + d.x; ar.y += b.y + d.y; ar.z += b.z + d.z; ar.w += b.w + d.w;
    }
    if (i < e) {
        int2 e0 = g_edge[i];
        float4 a = *(const float4*)(ent + (size_t)e0.x * FF + lane * 4);
        float4 b = *(const float4*)(rel + (size_t)e0.y * FF + lane * 4);
        ae.x += a.x; ae.y += a.y; ae.z += a.z; ae.w += a.w;
        ar.x += b.x; ar.y += b.y; ar.z += b.z; ar.w += b.w;
    }
    float inv = 1.f / fmaxf((float)(e - s), 1.f);
    float* oe = &g_out[0][(size_t)w * FD + lane * 4];
    float* orr = &g_out[1][(size_t)w * FD + lane * 4];
    oe[0] = tanhf(ae.x * inv); oe[1] = tanhf(ae.y * inv);
    oe[2] = tanhf(ae.z * inv); oe[3] = tanhf(ae.w * inv);
    orr[0] = tanhf(ar.x * inv); orr[1] = tanhf(ar.y * inv);
    orr[2] = tanhf(ar.z * inv); orr[3] = tanhf(ar.w * inv);
}

// ---- GNN layer: 1 warp/node handles BOTH duals (rn read once), 2-edge ILP ------
__global__ void __launch_bounds__(256) layer_kernel(int layer, int N_, int R_) {
    int w = (blockIdx.x * blockDim.x + threadIdx.x) >> 5;
    if (w >= N_) return;
    int lane = threadIdx.x & 31;
    int s = g_rowptr[w], e = g_rowptr[w + 1];
    const float* fe = g_out[0];
    const float* fr = g_out[1];
    const float* tt0 = g_ttab + (size_t)layer * R_;
    const float* tt1 = g_ttab + (size_t)(2 + layer) * R_;
    float smax0 = g_smax[(size_t)layer * N_ + w];
    float smax1 = g_smax[(size_t)(2 + layer) * N_ + w];
    float invs0 = (e > s) ? 1.f / g_ssum[(size_t)layer * N_ + w] : 0.f;
    float invs1 = (e > s) ? 1.f / g_ssum[(size_t)(2 + layer) * N_ + w] : 0.f;
    int coff = layer * FF + lane * 4;
    float4 accE = make_float4(0, 0, 0, 0), accR = make_float4(0, 0, 0, 0);

    for (int i = s; i < e; i += 2) {
        int i1 = min(i + 1, e - 1);
        float a1 = (i + 1 < e) ? 1.f : 0.f;
        int2 e0 = g_edge[i], e1 = g_edge[i1];
        float4 fe0 = *(const float4*)(fe + (size_t)e0.x * FD + coff);
        float4 fe1 = *(const float4*)(fe + (size_t)e1.x * FD + coff);
        float4 fr0 = *(const float4*)(fr + (size_t)e0.x * FD + coff);
        float4 fr1 = *(const float4*)(fr + (size_t)e1.x * FD + coff);
        float4 r0 = *(const float4*)(g_relnorm + (size_t)e0.y * FF + lane * 4);
        float4 r1 = *(const float4*)(g_relnorm + (size_t)e1.y * FF + lane * 4);
        float pe0 = fe0.x * r0.x + fe0.y * r0.y + fe0.z * r0.z + fe0.w * r0.w;
        float pe1 = fe1.x * r1.x + fe1.y * r1.y + fe1.z * r1.z + fe1.w * r1.w;
        float pr0 = fr0.x * r0.x + fr0.y * r0.y + fr0.z * r0.z + fr0.w * r0.w;
        float pr1 = fr1.x * r1.x + fr1.y * r1.y + fr1.z * r1.z + fr1.w * r1.w;
        // four independent butterfly chains
#pragma unroll
        for (int o = 16; o; o >>= 1) {
            pe0 += __shfl_xor_sync(0xffffffffu, pe0, o);
            pe1 += __shfl_xor_sync(0xffffffffu, pe1, o);
            pr0 += __shfl_xor_sync(0xffffffffu, pr0, o);
            pr1 += __shfl_xor_sync(0xffffffffu, pr1, o);
        }
        float we0 = __expf(tt0[e0.y] - smax0) * invs0;
        float we1 = __expf(tt0[e1.y] - smax0) * invs0 * a1;
        float wr0 = __expf(tt1[e0.y] - smax1) * invs1;
        float wr1 = __expf(tt1[e1.y] - smax1) * invs1 * a1;
        float ce0 = 2.f * pe0 * we0, ce1 = 2.f * pe1 * we1;
        float cr0 = 2.f * pr0 * wr0, cr1 = 2.f * pr1 * wr1;
        accE.x += we0 * fe0.x - ce0 * r0.x + we1 * fe1.x - ce1 * r1.x;
        accE.y += we0 * fe0.y - ce0 * r0.y + we1 * fe1.y - ce1 * r1.y;
        accE.z += we0 * fe0.z - ce0 * r0.z + we1 * fe1.z - ce1 * r1.z;
        accE.w += we0 * fe0.w - ce0 * r0.w + we1 * fe1.w - ce1 * r1.w;
        accR.x += wr0 * fr0.x - cr0 * r0.x + wr1 * fr1.x - cr1 * r1.x;
        accR.y += wr0 * fr0.y - cr0 * r0.y + wr1 * fr1.y - cr1 * r1.y;
        accR.z += wr0 * fr0.z - cr0 * r0.z + wr1 * fr1.z - cr1 * r1.z;
        accR.w += wr0 * fr0.w - cr0 * r0.w + wr1 * fr1.w - cr1 * r1.w;
    }
    float* oe = &g_out[0][(size_t)w * FD + (layer + 1) * FF + lane * 4];
    float* orr = &g_out[1][(size_t)w * FD + (layer + 1) * FF + lane * 4];
    oe[0] = tanhf(accE.x); oe[1] = tanhf(accE.y);
    oe[2] = tanhf(accE.z); oe[3] = tanhf(accE.w);
    orr[0] = tanhf(accR.x); orr[1] = tanhf(accR.y);
    orr[2] = tanhf(accR.z); orr[3] = tanhf(accR.w);
}

// --------- proxy normalization: write normalized + raw bf16 hi/lo ---------------
__global__ void pnorm_kernel(const float* __restrict__ pe, const float* __restrict__ pr) {
    int w = (blockIdx.x * blockDim.x + threadIdx.x) >> 5;
    if (w >= 2 * PP) return;
    int lane = threadIdx.x & 31;
    int dual = (w >= PP) ? 1 : 0;
    int row = w & (PP - 1);
    const float* p = dual ? pr : pe;
    float v[12];
    float ss = 0;
#pragma unroll
    for (int j = 0; j < 12; j++) {
        v[j] = p[(size_t)row * FD + lane + 32 * j];
        ss += v[j] * v[j];
    }
    ss = wsum(ss);
    float inv = 1.f / fmaxf(sqrtf(ss), EPSV);
#pragma unroll
    for (int j = 0; j < 12; j++) {
        int idx = row * FD + lane + 32 * j;
        __nv_bfloat16 h, l;
        split_bf16(v[j] * inv, h, l);
        g_pnh[dual][idx] = h; g_pnl[dual][idx] = l;
        split_bf16(v[j], h, l);
        g_ph[dual][idx] = h; g_pl[dual][idx] = l;
    }
}

// ------------------------ W -> bf16 hi/lo split ---------------------------------
__global__ void wconv_kernel(const float* __restrict__ We, const float* __restrict__ Wr) {
    int i = blockIdx.x * blockDim.x + threadIdx.x;
    if (i >= 2 * FD * FD) return;
    int dual = i >= FD * FD;
    int j = i - dual * FD * FD;
    float v = (dual ? Wr : We)[j];
    __nv_bfloat16 h, l;
    split_bf16(v, h, l);
    g_wh[dual][j] = h;
    g_wl[dual][j] = l;
}

#define ALD 40
#define SLD 68
#define BLD 72

// ------- S = l2norm(O) @ Pn^T (WMMA 3-term, in-kernel O conversion) -------------
__global__ void __launch_bounds__(256) s_wmma_kernel(int N_) {
    __shared__ __align__(16) char smraw[34816];
    __shared__ float ssqp[128][2];
    __nv_bfloat16* Ah = (__nv_bfloat16*)smraw;           // [128][ALD]
    __nv_bfloat16* Al = Ah + 128 * ALD;
    __nv_bfloat16* Bh = Al + 128 * ALD;                  // [64][ALD]
    __nv_bfloat16* Bl = Bh + 64 * ALD;
    float* stage = (float*)smraw;                        // [128][SLD]

    int tid = threadIdx.x, wid = tid >> 5, lane = tid & 31;
    int warpM = wid & 3, warpN = wid >> 2;
    int rowBase = blockIdx.x * 128;
    int dual = blockIdx.z;
    const float* O = g_out[dual];
    const unsigned* PNH = (const unsigned*)g_pnh[dual];
    const unsigned* PNL = (const unsigned*)g_pnl[dual];

    int arow = tid >> 1, ahalf = tid & 1;
    int agr = rowBase + arow;
    const float* aptr = O + (size_t)agr * FD + ahalf * 16;
    float myssq = 0.f;

    wmma::fragment<wmma::accumulator, 16, 16, 16, float> c[2][2];
#pragma unroll
    for (int i = 0; i < 2; i++)
#pragma unroll
        for (int j = 0; j < 2; j++) wmma::fill_fragment(c[i][j], 0.f);

    for (int k0 = 0; k0 < FD; k0 += 32) {
        {
            float v[16];
            if (agr < N_) {
#pragma unroll
                for (int q = 0; q < 4; q++)
                    *(float4*)(&v[q * 4]) = *(const float4*)(aptr + k0 + q * 4);
            } else {
#pragma unroll
                for (int j = 0; j < 16; j++) v[j] = 0.f;
            }
            __nv_bfloat162* dh = (__nv_bfloat162*)(Ah + arow * ALD) + ahalf * 8;
            __nv_bfloat162* dl = (__nv_bfloat162*)(Al + arow * ALD) + ahalf * 8;
#pragma unroll
            for (int j = 0; j < 8; j++) {
                __nv_bfloat16 h0, l0, h1, l1;
                split_bf16(v[2 * j], h0, l0);
                split_bf16(v[2 * j + 1], h1, l1);
                dh[j] = __nv_bfloat162(h0, h1);
                dl[j] = __nv_bfloat162(l0, l1);
                myssq = fmaf(v[2 * j], v[2 * j], myssq);
                myssq = fmaf(v[2 * j + 1], v[2 * j + 1], myssq);
            }
        }
        for (int s = tid; s < 1024; s += 256) {
            int br = s >> 4, cu = s & 15;
            size_t gi = ((size_t)br * FD + k0) / 2 + cu;
            ((unsigned*)(Bh + br * ALD))[cu] = PNH[gi];
            ((unsigned*)(Bl + br * ALD))[cu] = PNL[gi];
        }
        __syncthreads();
#pragma unroll
        for (int ks = 0; ks < 32; ks += 16) {
            wmma::fragment<wmma::matrix_a, 16, 16, 16, __nv_bfloat16, wmma::row_major> a[2];
            wmma::fragment<wmma::matrix_b, 16, 16, 16, __nv_bfloat16, wmma::col_major> b[2];
            // term 1: Ah x Bh
#pragma unroll
            for (int i = 0; i < 2; i++)
                wmma::load_matrix_sync(a[i], Ah + (warpM * 32 + i * 16) * ALD + ks, ALD);
#pragma unroll
            for (int j = 0; j < 2; j++)
                wmma::load_matrix_sync(b[j], Bh + (warpN * 32 + j * 16) * ALD + ks, ALD);
#pragma unroll
            for (int i = 0; i < 2; i++)
#pragma unroll
                for (int j = 0; j < 2; j++) wmma::mma_sync(c[i][j], a[i], b[j], c[i][j]);
            // term 2: Ah x Bl (reuse a)
#pragma unroll
            for (int j = 0; j < 2; j++)
                wmma::load_matrix_sync(b[j], Bl + (warpN * 32 + j * 16) * ALD + ks, ALD);
#pragma unroll
            for (int i = 0; i < 2; i++)
#pragma unroll
                for (int j = 0; j < 2; j++) wmma::mma_sync(c[i][j], a[i], b[j], c[i][j]);
            // term 3: Al x Bh
#pragma unroll
            for (int i = 0; i < 2; i++)
                wmma::load_matrix_sync(a[i], Al + (warpM * 32 + i * 16) * ALD + ks, ALD);
#pragma unroll
            for (int j = 0; j < 2; j++)
                wmma::load_matrix_sync(b[j], Bh + (warpN * 32 + j * 16) * ALD + ks, ALD);
#pragma unroll
            for (int i = 0; i < 2; i++)
#pragma unroll
                for (int j = 0; j < 2; j++) wmma::mma_sync(c[i][j], a[i], b[j], c[i][j]);
        }
        __syncthreads();
    }
    ssqp[arow][ahalf] = myssq;

#pragma unroll
    for (int i = 0; i < 2; i++)
#pragma unroll
        for (int j = 0; j < 2; j++)
            wmma::store_matrix_sync(stage + (warpM * 32 + i * 16) * SLD + warpN * 32 + j * 16,
                                    c[i][j], SLD, wmma::mem_row_major);
    __syncthreads();

    __nv_bfloat162* ATTH = (__nv_bfloat162*)g_atth[dual];
    __nv_bfloat162* ATTL = (__nv_bfloat162*)g_attl[dual];
#pragma unroll
    for (int i = 0; i < 16; i++) {
        int r = wid * 16 + i;
        int n = rowBase + r;
        float inv = 0.f;
        if (n < N_) inv = 1.f / fmaxf(sqrtf(ssqp[r][0] + ssqp[r][1]), EPSV);
        float v0 = stage[r * SLD + lane * 2] * inv;
        float v1 = stage[r * SLD + lane * 2 + 1] * inv;
        float m = fmaxf(v0, v1);
#pragma unroll
        for (int o = 16; o; o >>= 1) m = fmaxf(m, __shfl_xor_sync(0xffffffffu, m, o));
        float e0 = __expf(v0 - m), e1 = __expf(v1 - m);
        float sm = e0 + e1;
#pragma unroll
        for (int o = 16; o; o >>= 1) sm += __shfl_xor_sync(0xffffffffu, sm, o);
        float rc = 1.f / sm;
        if (n < N_) {
            float a0 = e0 * rc, a1 = e1 * rc;
            __nv_bfloat16 h0, l0, h1, l1;
            split_bf16(a0, h0, l0);
            split_bf16(a1, h1, l1);
            size_t bi = ((size_t)n * PP + lane * 2) >> 1;
            ATTH[bi] = __nv_bfloat162(h0, h1);
            ATTL[bi] = __nv_bfloat162(l0, l1);
        }
    }
}

// ------- PF = O - Att @ P (WMMA 3-term, K=64) -> bf16 hi/lo ---------------------
__global__ void __launch_bounds__(256) pf_wmma_kernel(int N_) {
    __shared__ __align__(16) char smraw[34816];
    __nv_bfloat16* Ah = (__nv_bfloat16*)smraw;           // [128][ALD]
    __nv_bfloat16* Al = Ah + 128 * ALD;
    __nv_bfloat16* Bh = Al + 128 * ALD;                  // [32 k][BLD cols]
    __nv_bfloat16* Bl = Bh + 32 * BLD;
    float* stage = (float*)smraw;                        // [128][SLD]

    int tid = threadIdx.x, wid = tid >> 5, lane = tid & 31;
    int warpM = wid & 3, warpN = wid >> 2;
    int colBase = blockIdx.x * 64;
    int rowBase = blockIdx.y * 128;
    int dual = blockIdx.z;
    const unsigned* ATH = (const unsigned*)g_atth[dual];
    const unsigned* ATL = (const unsigned*)g_attl[dual];
    const unsigned* PH = (const unsigned*)g_ph[dual];
    const unsigned* PL = (const unsigned*)g_pl[dual];

    wmma::fragment<wmma::accumulator, 16, 16, 16, float> c[2][2];
#pragma unroll
    for (int i = 0; i < 2; i++)
#pragma unroll
        for (int j = 0; j < 2; j++) wmma::fill_fragment(c[i][j], 0.f);

    for (int k0 = 0; k0 < PP; k0 += 32) {
        for (int s = tid; s < 2048; s += 256) {
            int r = s >> 4, cu = s & 15;
            int gr = rowBase + r;
            unsigned vh = 0, vl = 0;
            if (gr < N_) {
                size_t gi = ((size_t)gr * PP + k0) / 2 + cu;
                vh = ATH[gi]; vl = ATL[gi];
            }
            ((unsigned*)(Ah + r * ALD))[cu] = vh;
            ((unsigned*)(Al + r * ALD))[cu] = vl;
        }
        for (int s = tid; s < 1024; s += 256) {
            int k = s >> 5, cp = s & 31;
            size_t gi = ((size_t)(k0 + k) * FD + colBase) / 2 + cp;
            ((unsigned*)(Bh + k * BLD))[cp] = PH[gi];
            ((unsigned*)(Bl + k * BLD))[cp] = PL[gi];
        }
        __syncthreads();
#pragma unroll
        for (int ks = 0; ks < 32; ks += 16) {
            wmma::fragment<wmma::matrix_a, 16, 16, 16, __nv_bfloat16, wmma::row_major> a[2];
            wmma::fragment<wmma::matrix_b, 16, 16, 16, __nv_bfloat16, wmma::row_major> b[2];
            // term 1: Ah x Bh
#pragma unroll
            for (int i = 0; i < 2; i++)
                wmma::load_matrix_sync(a[i], Ah + (warpM * 32 + i * 16) * ALD + ks, ALD);
#pragma unroll
            for (int j = 0; j < 2; j++)
                wmma::load_matrix_sync(b[j], Bh + ks * BLD + warpN * 32 + j * 16, BLD);
#pragma unroll
            for (int i = 0; i < 2; i++)
#pragma unroll
                for (int j = 0; j < 2; j++) wmma::mma_sync(c[i][j], a[i], b[j], c[i][j]);
            // term 2: Ah x Bl (reuse a)
#pragma unroll
            for (int j = 0; j < 2; j++)
                wmma::load_matrix_sync(b[j], Bl + ks * BLD + warpN * 32 + j * 16, BLD);
#pragma unroll
            for (int i = 0; i < 2; i++)
#pragma unroll
                for (int j = 0; j < 2; j++) wmma::mma_sync(c[i][j], a[i], b[j], c[i][j]);
            // term 3: Al x Bh
#pragma unroll
            for (int i = 0; i < 2; i++)
                wmma::load_matrix_sync(a[i], Al + (warpM * 32 + i * 16) * ALD + ks, ALD);
#pragma unroll
            for (int j = 0; j < 2; j++)
                wmma::load_matrix_sync(b[j], Bh + ks * BLD + warpN * 32 + j * 16, BLD);
#pragma unroll
            for (int i = 0; i < 2; i++)
#pragma unroll
                for (int j = 0; j < 2; j++) wmma::mma_sync(c[i][j], a[i], b[j], c[i][j]);
        }
        __syncthreads();
    }

#pragma unroll
    for (int i = 0; i < 2; i++)
#pragma unroll
        for (int j = 0; j < 2; j++)
            wmma::store_matrix_sync(stage + (warpM * 32 + i * 16) * SLD + warpN * 32 + j * 16,
                                    c[i][j], SLD, wmma::mem_row_major);
    __syncthreads();

    const float* O = g_out[dual];
    __nv_bfloat162* DH = (__nv_bfloat162*)g_pfh[dual];
    __nv_bfloat162* DL = (__nv_bfloat162*)g_pfl[dual];
#pragma unroll
    for (int i = 0; i < 16; i++) {
        int r = wid * 16 + i;
        int n = rowBase + r;
        if (n >= N_) continue;
        int c0 = colBase + lane * 2;
        float2 acc = *(float2*)(stage + r * SLD + lane * 2);
        float2 ov = *(const float2*)(O + (size_t)n * FD + c0);
        float va = ov.x - acc.x;
        float vb = ov.y - acc.y;
        __nv_bfloat16 ha, la, hb, lb;
        split_bf16(va, ha, la);
        split_bf16(vb, hb, lb);
        size_t bi = ((size_t)n * FD + c0) >> 1;
        DH[bi] = __nv_bfloat162(ha, hb);
        DL[bi] = __nv_bfloat162(la, lb);
    }
}

// ------- F2: WMMA bf16 3-term split GEMM + sigmoid blend ------------------------
__global__ void __launch_bounds__(256) f2_wmma_kernel(const float* __restrict__ be,
                                                      const float* __restrict__ br,
                                                      float* __restrict__ out, int N_) {
    __shared__ __align__(16) char smraw[34816];
    __nv_bfloat16* Ah = (__nv_bfloat16*)smraw;           // [128][ALD]
    __nv_bfloat16* Al = Ah + 128 * ALD;
    __nv_bfloat16* Bh = Al + 128 * ALD;                  // [64][ALD] (n-major, k inner)
    __nv_bfloat16* Bl = Bh + 64 * ALD;
    float* stage = (float*)smraw;                        // [128][SLD]

    int tid = threadIdx.x, wid = tid >> 5, lane = tid & 31;
    int warpM = wid & 3, warpN = wid >> 2;
    int colBase = blockIdx.x * 64;
    int rowBase = blockIdx.y * 128;
    int dual = blockIdx.z;
    const float* bias = dual ? br : be;
    const __nv_bfloat16* PH = g_pfh[dual];
    const __nv_bfloat16* PL = g_pfl[dual];
    const __nv_bfloat16* WH = g_wh[dual];
    const __nv_bfloat16* WL = g_wl[dual];

    wmma::fragment<wmma::accumulator, 16, 16, 16, float> c[2][2];
#pragma unroll
    for (int i = 0; i < 2; i++)
#pragma unroll
        for (int j = 0; j < 2; j++) wmma::fill_fragment(c[i][j], 0.f);

    for (int k0 = 0; k0 < FD; k0 += 32) {
        for (int s = tid; s < 2048; s += 256) {
            int r = s >> 4, cu = s & 15;
            int gr = rowBase + r;
            unsigned vh = 0, vl = 0;
            if (gr < N_) {
                size_t gi = ((size_t)gr * FD + k0) / 2 + cu;
                vh = ((const unsigned*)PH)[gi];
                vl = ((const unsigned*)PL)[gi];
            }
            ((unsigned*)(Ah + r * ALD))[cu] = vh;
            ((unsigned*)(Al + r * ALD))[cu] = vl;
        }
        for (int s = tid; s < 64 * 32; s += 256) {
            int n = s & 63, k = s >> 6;
            size_t gi = (size_t)(k0 + k) * FD + colBase + n;
            Bh[n * ALD + k] = WH[gi];
            Bl[n * ALD + k] = WL[gi];
        }
        __syncthreads();
#pragma unroll
        for (int ks = 0; ks < 32; ks += 16) {
            wmma::fragment<wmma::matrix_a, 16, 16, 16, __nv_bfloat16, wmma::row_major> a[2];
            wmma::fragment<wmma::matrix_b, 16, 16, 16, __nv_bfloat16, wmma::col_major> b[2];
            // term 1: Ah x Bh
#pragma unroll
            for (int i = 0; i < 2; i++)
                wmma::load_matrix_sync(a[i], Ah + (warpM * 32 + i * 16) * ALD + ks, ALD);
#pragma unroll
            for (int j = 0; j < 2; j++)
                wmma::load_matrix_sync(b[j], Bh + (warpN * 32 + j * 16) * ALD + ks, ALD);
#pragma unroll
            for (int i = 0; i < 2; i++)
#pragma unroll
                for (int j = 0; j < 2; j++) wmma::mma_sync(c[i][j], a[i], b[j], c[i][j]);
            // term 2: Ah x Bl (reuse a)
#pragma unroll
            for (int j = 0; j < 2; j++)
                wmma::load_matrix_sync(b[j], Bl + (warpN * 32 + j * 16) * ALD + ks, ALD);
#pragma unroll
            for (int i = 0; i < 2; i++)
#pragma unroll
                for (int j = 0; j < 2; j++) wmma::mma_sync(c[i][j], a[i], b[j], c[i][j]);
            // term 3: Al x Bh
#pragma unroll
            for (int i = 0; i < 2; i++)
                wmma::load_matrix_sync(a[i], Al + (warpM * 32 + i * 16) * ALD + ks, ALD);
#pragma unroll
            for (int j = 0; j < 2; j++)
                wmma::load_matrix_sync(b[j], Bh + (warpN * 32 + j * 16) * ALD + ks, ALD);
#pragma unroll
            for (int i = 0; i < 2; i++)
#pragma unroll
                for (int j = 0; j < 2; j++) wmma::mma_sync(c[i][j], a[i], b[j], c[i][j]);
        }
        __syncthreads();
    }

#pragma unroll
    for (int i = 0; i < 2; i++)
#pragma unroll
        for (int j = 0; j < 2; j++)
            wmma::store_matrix_sync(stage + (warpM * 32 + i * 16) * SLD + warpN * 32 + j * 16,
                                    c[i][j], SLD, wmma::mem_row_major);
    __syncthreads();

    const float* O = g_out[dual];
    const __nv_bfloat162* PH2 = (const __nv_bfloat162*)PH;
    const __nv_bfloat162* PL2 = (const __nv_bfloat162*)PL;
#pragma unroll
    for (int i = 0; i < 16; i++) {
        int r = wid * 16 + i;
        int n = rowBase + r;
        if (n >= N_) continue;
        int c0 = colBase + lane * 2;
        float2 acc = *(float2*)(stage + r * SLD + lane * 2);
        float2 bv = *(const float2*)(bias + c0);
        float2 ov = *(const float2*)(O + (size_t)n * FD + c0);
        size_t pi = ((size_t)n * FD + c0) >> 1;
        __nv_bfloat162 h0 = PH2[pi];
        __nv_bfloat162 l0 = PL2[pi];
        float pf0 = __bfloat162float(h0.x) + __bfloat162float(l0.x);
        float pf1 = __bfloat162float(h0.y) + __bfloat162float(l0.y);
        float g0 = 1.f / (1.f + __expf(-(acc.x + bv.x)));
        float g1 = 1.f / (1.f + __expf(-(acc.y + bv.y)));
        float2 res;
        res.x = g0 * ov.x + (1.f - g0) * pf0;
        res.y = g1 * ov.y + (1.f - g1) * pf1;
        *(float2*)(out + (size_t)n * (2 * FD) + dual * FD + c0) = res;
    }
}

// ------------------------ launch ------------------------------------------------
extern "C" void kernel_launch(void* const* d_in, const int* in_sizes, int n_in,
                              void* d_out, int out_size) {
    const float* ent_emb = (const float*)d_in[0];
    const float* rel_emb = (const float*)d_in[1];
    const int* edge_src  = (const int*)d_in[2];
    const int* edge_dst  = (const int*)d_in[3];
    const int* edge_rel  = (const int*)d_in[4];
    const float* attn_e  = (const float*)d_in[5];
    const float* gate_e  = (const float*)d_in[6];
    const float* proxy_e = (const float*)d_in[7];
    const float* bias_e  = (const float*)d_in[8];
    const float* attn_r  = (const float*)d_in[9];
    const float* gate_r  = (const float*)d_in[10];
    const float* proxy_r = (const float*)d_in[11];
    const float* bias_r  = (const float*)d_in[12];

    int N_ = in_sizes[0] / FF;
    int R_ = in_sizes[1] / FF;
    int E_ = in_sizes[2];
    float* out = (float*)d_out;

    zero_deg_kernel<<<(N_ + 255) / 256, 256>>>(N_);
    count_kernel<<<(E_ + 255) / 256, 256>>>(edge_dst, E_);
    scan_kernel<<<1, 1024>>>(N_);
    scatter_kernel<<<(E_ + 255) / 256, 256>>>(edge_dst, edge_src, edge_rel, E_);
    relnorm_kernel<<<(R_ * 32 + 255) / 256, 256>>>(rel_emb, attn_e, attn_r, R_);
    stats_kernel<<<1184, 256>>>(N_, R_);
    init_kernel<<<(N_ * 32 + 255) / 256, 256>>>(ent_emb, rel_emb, N_);
    wconv_kernel<<<(2 * FD * FD + 255) / 256, 256>>>(gate_e, gate_r);
    pnorm_kernel<<<16, 256>>>(proxy_e, proxy_r);

    int lgrid = (N_ * 32 + 255) / 256;
    layer_kernel<<<lgrid, 256>>>(0, N_, R_);
    layer_kernel<<<lgrid, 256>>>(1, N_, R_);

    int rb = (N_ + 127) / 128;
    dim3 gs(rb, 1, 2);
    s_wmma_kernel<<<gs, 256>>>(N_);

    dim3 gpf(FD / 64, rb, 2);
    pf_wmma_kernel<<<gpf, 256>>>(N_);

    dim3 g2(FD / 64, rb, 2);
    f2_wmma_kernel<<<g2, 256>>>(bias_e, bias_r, out, N_);
}